// round 1
// baseline (speedup 1.0000x reference)
#include <cuda_runtime.h>

#define BB 4
#define QL 1024
#define DM 1024
#define NHEAD 16
#define DH 64
#define MTOT (BB * QL)  // 4096

// Scratch (no allocations allowed)
__device__ float g_qh[(size_t)MTOT * DM];
__device__ float g_kh[(size_t)MTOT * DM];
__device__ float g_vh[(size_t)MTOT * DM];
__device__ float g_av[(size_t)MTOT * DM];
__device__ float g_ao[(size_t)MTOT * DM];

// ---------------------------------------------------------------------------
// Classic 128x128x8 SGEMM, row-major A[M,K] @ B[K,N] -> C[M,N].
// 256 threads, 8x8 micro-tile per thread. M,N,K multiples of 128/128/8.
// ---------------------------------------------------------------------------
__global__ __launch_bounds__(256) void sgemm128(
    const float* __restrict__ A, const float* __restrict__ B,
    float* __restrict__ C, int M, int N, int K)
{
    __shared__ float As[8][128];
    __shared__ float Bs[8][128];

    const int tid = threadIdx.x;
    const int tx = tid & 15, ty = tid >> 4;
    const int row0 = blockIdx.y * 128, col0 = blockIdx.x * 128;

    const int arow = tid >> 1, acol = (tid & 1) << 2;
    const int brow = tid >> 5, bcol = (tid & 31) << 2;

    const float* Ap = A + (size_t)(row0 + arow) * K + acol;
    const float* Bp = B + (size_t)brow * N + col0 + bcol;

    float acc[8][8];
#pragma unroll
    for (int i = 0; i < 8; ++i)
#pragma unroll
        for (int j = 0; j < 8; ++j) acc[i][j] = 0.f;

    for (int k0 = 0; k0 < K; k0 += 8) {
        float4 a4 = *(const float4*)Ap;
        float4 b4 = *(const float4*)Bp;
        Ap += 8;
        Bp += (size_t)8 * N;
        __syncthreads();
        As[acol + 0][arow] = a4.x;
        As[acol + 1][arow] = a4.y;
        As[acol + 2][arow] = a4.z;
        As[acol + 3][arow] = a4.w;
        *(float4*)&Bs[brow][bcol] = b4;
        __syncthreads();
#pragma unroll
        for (int k = 0; k < 8; ++k) {
            float a[8], bv[8];
            *(float4*)&a[0] = *(const float4*)&As[k][ty * 4];
            *(float4*)&a[4] = *(const float4*)&As[k][64 + ty * 4];
            *(float4*)&bv[0] = *(const float4*)&Bs[k][tx * 4];
            *(float4*)&bv[4] = *(const float4*)&Bs[k][64 + tx * 4];
#pragma unroll
            for (int i = 0; i < 8; ++i)
#pragma unroll
                for (int j = 0; j < 8; ++j) acc[i][j] += a[i] * bv[j];
        }
    }

#pragma unroll
    for (int ih = 0; ih < 2; ++ih)
#pragma unroll
        for (int i = 0; i < 4; ++i) {
            const int r = row0 + ih * 64 + ty * 4 + i;
            float* cp = C + (size_t)r * N + col0;
            const int ai = ih * 4 + i;
            *(float4*)(cp + tx * 4) =
                make_float4(acc[ai][0], acc[ai][1], acc[ai][2], acc[ai][3]);
            *(float4*)(cp + 64 + tx * 4) =
                make_float4(acc[ai][4], acc[ai][5], acc[ai][6], acc[ai][7]);
        }
}

// ---------------------------------------------------------------------------
// Fused rel-attention, flash style. One CTA = (b, head, 64-query tile).
// score[i,j] = q_i . (k_j + r_emb[j+1])  +  (r_w_bias . k_j + r_bias[j+1])
// (shifted terms are zero at j = QL-1). Online softmax over j.
// ---------------------------------------------------------------------------
__global__ __launch_bounds__(256) void attn_kernel(
    const float* __restrict__ qh, const float* __restrict__ kh,
    const float* __restrict__ vh, const float* __restrict__ remb,
    const float* __restrict__ rwb, const float* __restrict__ rbias,
    float* __restrict__ av)
{
    extern __shared__ float smem[];
    float* sq   = smem;            // [64][68]  q transposed: sq[d*68 + i]
    float* sc   = smem + 64 * 68;  // [64][68]  combined key transposed; reused as P[i*68+j]
    float* sv   = sc + 64 * 68;    // [64][64]  v: sv[j*64 + d]
    float* ts   = sv + 64 * 64;    // [64]      per-key scalar term
    float* rwbs = ts + 64;         // [64]      r_w_bias for this head

    const int tid = threadIdx.x;
    const int qt = blockIdx.x, n = blockIdx.y, b = blockIdx.z;
    const int i0 = qt * 64;

    if (tid < 64) rwbs[tid] = rwb[n * DH + tid];

    const int lr = tid >> 2;         // row 0..63 handled by 4 threads
    const int lc = (tid & 3) << 2;   // 0,4,8,12 (+16*c chunks)

    // Q tile -> transposed smem
    {
        const float* qp = qh + (size_t)(b * QL + i0 + lr) * DM + n * DH + lc;
#pragma unroll
        for (int c = 0; c < 64; c += 16) {
            float4 q4 = *(const float4*)(qp + c);
            sq[(lc + c + 0) * 68 + lr] = q4.x;
            sq[(lc + c + 1) * 68 + lr] = q4.y;
            sq[(lc + c + 2) * 68 + lr] = q4.z;
            sq[(lc + c + 3) * 68 + lr] = q4.w;
        }
    }

    const int tx = tid & 15, ty = tid >> 4;
    float o[4][4];
    float rm[4], rl[4];
#pragma unroll
    for (int i = 0; i < 4; ++i) {
        rm[i] = -1e30f;
        rl[i] = 0.f;
#pragma unroll
        for (int j = 0; j < 4; ++j) o[i][j] = 0.f;
    }

    for (int jt = 0; jt < 16; ++jt) {
        const int j0 = jt * 64;
        __syncthreads();  // previous tile fully consumed (also covers Q store at jt=0)
        {
            const int gj = j0 + lr;
            const float* kp = kh + (size_t)(b * QL + gj) * DM + n * DH + lc;
            const float* vp = vh + (size_t)(b * QL + gj) * DM + n * DH + lc;
            const bool has = (gj + 1 < QL);
            const float* rp = remb + ((size_t)(gj + 1) * NHEAD + n) * DH + lc;
            float tp = 0.f;
#pragma unroll
            for (int c = 0; c < 64; c += 16) {
                float4 k4 = *(const float4*)(kp + c);
                float4 v4 = *(const float4*)(vp + c);
                float4 r4 = has ? *(const float4*)(rp + c)
                                : make_float4(0.f, 0.f, 0.f, 0.f);
                sc[(lc + c + 0) * 68 + lr] = k4.x + r4.x;
                sc[(lc + c + 1) * 68 + lr] = k4.y + r4.y;
                sc[(lc + c + 2) * 68 + lr] = k4.z + r4.z;
                sc[(lc + c + 3) * 68 + lr] = k4.w + r4.w;
                *(float4*)&sv[lr * 64 + lc + c] = v4;
                tp += k4.x * rwbs[lc + c + 0] + k4.y * rwbs[lc + c + 1] +
                      k4.z * rwbs[lc + c + 2] + k4.w * rwbs[lc + c + 3];
            }
            tp += __shfl_xor_sync(0xffffffffu, tp, 1);
            tp += __shfl_xor_sync(0xffffffffu, tp, 2);
            if ((tid & 3) == 0)
                ts[lr] = tp + (has ? rbias[(size_t)(gj + 1) * NHEAD + n] : 0.f);
        }
        __syncthreads();

        // S tile: rows 4*ty+i, cols 4*tx+j
        float s[4][4];
#pragma unroll
        for (int i = 0; i < 4; ++i)
#pragma unroll
            for (int j = 0; j < 4; ++j) s[i][j] = 0.f;

#pragma unroll 4
        for (int d = 0; d < 64; ++d) {
            float4 a4 = *(const float4*)&sq[d * 68 + 4 * ty];
            float4 b4 = *(const float4*)&sc[d * 68 + 4 * tx];
            float a[4] = {a4.x, a4.y, a4.z, a4.w};
            float bv[4] = {b4.x, b4.y, b4.z, b4.w};
#pragma unroll
            for (int i = 0; i < 4; ++i)
#pragma unroll
                for (int j = 0; j < 4; ++j) s[i][j] += a[i] * bv[j];
        }

#pragma unroll
        for (int i = 0; i < 4; ++i)
#pragma unroll
            for (int j = 0; j < 4; ++j)
                s[i][j] = (s[i][j] + ts[4 * tx + j]) * 0.125f;

        __syncthreads();  // done reading sc/ts; sc will be reused for P

        // online softmax update + P store
#pragma unroll
        for (int i = 0; i < 4; ++i) {
            float mx = fmaxf(fmaxf(s[i][0], s[i][1]), fmaxf(s[i][2], s[i][3]));
            mx = fmaxf(mx, __shfl_xor_sync(0xffffffffu, mx, 1));
            mx = fmaxf(mx, __shfl_xor_sync(0xffffffffu, mx, 2));
            mx = fmaxf(mx, __shfl_xor_sync(0xffffffffu, mx, 4));
            mx = fmaxf(mx, __shfl_xor_sync(0xffffffffu, mx, 8));
            const float mnew = fmaxf(rm[i], mx);
            const float alpha = __expf(rm[i] - mnew);
            rm[i] = mnew;
            float sum = 0.f;
#pragma unroll
            for (int j = 0; j < 4; ++j) {
                const float p = __expf(s[i][j] - mnew);
                sum += p;
                sc[(4 * ty + i) * 68 + 4 * tx + j] = p;
            }
            sum += __shfl_xor_sync(0xffffffffu, sum, 1);
            sum += __shfl_xor_sync(0xffffffffu, sum, 2);
            sum += __shfl_xor_sync(0xffffffffu, sum, 4);
            sum += __shfl_xor_sync(0xffffffffu, sum, 8);
            rl[i] = rl[i] * alpha + sum;
#pragma unroll
            for (int j = 0; j < 4; ++j) o[i][j] *= alpha;
        }
        __syncthreads();

        // O += P @ V  (O cols 4*tx..4*tx+3 of DH)
#pragma unroll 4
        for (int j = 0; j < 64; ++j) {
            float4 v4 = *(const float4*)&sv[j * 64 + 4 * tx];
#pragma unroll
            for (int i = 0; i < 4; ++i) {
                const float p = sc[(4 * ty + i) * 68 + j];
                o[i][0] += p * v4.x;
                o[i][1] += p * v4.y;
                o[i][2] += p * v4.z;
                o[i][3] += p * v4.w;
            }
        }
    }

#pragma unroll
    for (int i = 0; i < 4; ++i) {
        const float inv = 1.f / rl[i];
        float4 r = make_float4(o[i][0] * inv, o[i][1] * inv,
                               o[i][2] * inv, o[i][3] * inv);
        *(float4*)&av[(size_t)(b * QL + i0 + 4 * ty + i) * DM + n * DH + 4 * tx] = r;
    }
}

// ---------------------------------------------------------------------------
// Residual + LayerNorm: out = LN(w + attn_out) * gamma + beta. One CTA/row.
// ---------------------------------------------------------------------------
__global__ __launch_bounds__(256) void ln_kernel(
    const float* __restrict__ w, const float* __restrict__ ao,
    const float* __restrict__ gamma, const float* __restrict__ beta,
    float* __restrict__ out)
{
    __shared__ float ssum[8], ssq[8];
    const int row = blockIdx.x;
    const int tid = threadIdx.x;
    const size_t base = (size_t)row * DM + tid * 4;

    float4 x = *(const float4*)(w + base);
    float4 a = *(const float4*)(ao + base);
    x.x += a.x; x.y += a.y; x.z += a.z; x.w += a.w;

    float sum = x.x + x.y + x.z + x.w;
    float sq = x.x * x.x + x.y * x.y + x.z * x.z + x.w * x.w;
#pragma unroll
    for (int off = 16; off; off >>= 1) {
        sum += __shfl_xor_sync(0xffffffffu, sum, off);
        sq += __shfl_xor_sync(0xffffffffu, sq, off);
    }
    const int wid = tid >> 5;
    if ((tid & 31) == 0) { ssum[wid] = sum; ssq[wid] = sq; }
    __syncthreads();
    sum = 0.f; sq = 0.f;
#pragma unroll
    for (int i = 0; i < 8; ++i) { sum += ssum[i]; sq += ssq[i]; }

    const float mu = sum * (1.f / DM);
    const float var = sq * (1.f / DM) - mu * mu;
    const float inv = rsqrtf(var + 1e-5f);

    float4 g = *(const float4*)(gamma + (size_t)tid * 4);
    float4 be = *(const float4*)(beta + (size_t)tid * 4);
    float4 r;
    r.x = (x.x - mu) * inv * g.x + be.x;
    r.y = (x.y - mu) * inv * g.y + be.y;
    r.z = (x.z - mu) * inv * g.z + be.z;
    r.w = (x.w - mu) * inv * g.w + be.w;
    *(float4*)(out + base) = r;
}

// ---------------------------------------------------------------------------
extern "C" void kernel_launch(void* const* d_in, const int* in_sizes, int n_in,
                              void* d_out, int out_size)
{
    (void)in_sizes; (void)n_in; (void)out_size;
    const float* w      = (const float*)d_in[0];
    const float* r_emb  = (const float*)d_in[1];
    const float* r_w_b  = (const float*)d_in[2];
    const float* r_bias = (const float*)d_in[3];
    const float* Wq     = (const float*)d_in[4];
    const float* Wk     = (const float*)d_in[5];
    const float* Wv     = (const float*)d_in[6];
    const float* Wo     = (const float*)d_in[7];
    const float* gamma  = (const float*)d_in[8];
    const float* beta   = (const float*)d_in[9];
    float* out = (float*)d_out;

    float *qh, *kh, *vh, *av, *ao;
    cudaGetSymbolAddress((void**)&qh, g_qh);
    cudaGetSymbolAddress((void**)&kh, g_kh);
    cudaGetSymbolAddress((void**)&vh, g_vh);
    cudaGetSymbolAddress((void**)&av, g_av);
    cudaGetSymbolAddress((void**)&ao, g_ao);

    dim3 gg(DM / 128, MTOT / 128);  // (8, 32)
    sgemm128<<<gg, 256>>>(w, Wq, qh, MTOT, DM, DM);
    sgemm128<<<gg, 256>>>(w, Wk, kh, MTOT, DM, DM);
    sgemm128<<<gg, 256>>>(w, Wv, vh, MTOT, DM, DM);

    const int smem_attn = (64 * 68 * 2 + 64 * 64 + 64 + 64) * 4;  // 51712 B
    cudaFuncSetAttribute(attn_kernel,
                         cudaFuncAttributeMaxDynamicSharedMemorySize, smem_attn);
    attn_kernel<<<dim3(QL / 64, NHEAD, BB), 256, smem_attn>>>(
        qh, kh, vh, r_emb, r_w_b, r_bias, av);

    sgemm128<<<gg, 256>>>(av, Wo, ao, MTOT, DM, DM);
    ln_kernel<<<MTOT, 256>>>(w, ao, gamma, beta, out);
}

// round 3
// speedup vs baseline: 1.5957x; 1.5957x over previous
#include <cuda_runtime.h>
#include <cuda_bf16.h>
#include <cstdint>

#define BB 4
#define QL 1024
#define DM 1024
#define NHEAD 16
#define DH 64
#define MTOT (BB * QL)  // 4096

// fp32 scratch
__device__ float g_qh[(size_t)MTOT * DM];
__device__ float g_kh[(size_t)MTOT * DM];
__device__ float g_vh[(size_t)MTOT * DM];
__device__ float g_av[(size_t)MTOT * DM];
__device__ float g_ao[(size_t)MTOT * DM];
// bf16 split operands
__device__ __nv_bfloat16 g_wh[(size_t)MTOT * DM];
__device__ __nv_bfloat16 g_wl[(size_t)MTOT * DM];
__device__ __nv_bfloat16 g_avh[(size_t)MTOT * DM];
__device__ __nv_bfloat16 g_avl[(size_t)MTOT * DM];
__device__ __nv_bfloat16 g_bh[(size_t)4 * DM * DM];  // weights [N,K] hi
__device__ __nv_bfloat16 g_bl[(size_t)4 * DM * DM];  // weights [N,K] lo

// ===========================================================================
// PTX helpers (portable: sm_80-class only)
// ===========================================================================
__device__ __forceinline__ uint32_t smem_to_u32(const void* p) {
    uint32_t a;
    asm("{ .reg .u64 t; cvta.to.shared.u64 t, %1; cvt.u32.u64 %0, t; }"
        : "=r"(a) : "l"(p));
    return a;
}
#define CP_ASYNC16(s, g) \
    asm volatile("cp.async.cg.shared.global [%0], [%1], 16;" :: "r"(s), "l"(g) : "memory")
#define CP_ASYNC_COMMIT() asm volatile("cp.async.commit_group;" ::: "memory")
#define CP_ASYNC_WAIT2() asm volatile("cp.async.wait_group 2;" ::: "memory")

#define LDSM4(r0, r1, r2, r3, addr)                                            \
    asm volatile("ldmatrix.sync.aligned.m8n8.x4.shared.b16 {%0,%1,%2,%3}, [%4];" \
                 : "=r"(r0), "=r"(r1), "=r"(r2), "=r"(r3) : "r"(addr))

#define MMA_BF16(d, a, b)                                                      \
    asm volatile("mma.sync.aligned.m16n8k16.row.col.f32.bf16.bf16.f32 "        \
                 "{%0,%1,%2,%3}, {%4,%5,%6,%7}, {%8,%9}, {%0,%1,%2,%3};"       \
                 : "+f"((d)[0]), "+f"((d)[1]), "+f"((d)[2]), "+f"((d)[3])      \
                 : "r"((a)[0]), "r"((a)[1]), "r"((a)[2]), "r"((a)[3]),         \
                   "r"((b)[0]), "r"((b)[1]))

// ===========================================================================
// Split fp32 -> bf16 hi + bf16 lo (elementwise, float4 x bf16x4)
// ===========================================================================
__global__ __launch_bounds__(256) void split_act(
    const float* __restrict__ in, __nv_bfloat16* __restrict__ hi,
    __nv_bfloat16* __restrict__ lo, int n4)
{
    int i = blockIdx.x * 256 + threadIdx.x;
    if (i >= n4) return;
    float4 a = ((const float4*)in)[i];
    __nv_bfloat16 h0 = __float2bfloat16(a.x), h1 = __float2bfloat16(a.y);
    __nv_bfloat16 h2 = __float2bfloat16(a.z), h3 = __float2bfloat16(a.w);
    __nv_bfloat162 H0 = __halves2bfloat162(h0, h1), H1 = __halves2bfloat162(h2, h3);
    ((__nv_bfloat162*)hi)[i * 2 + 0] = H0;
    ((__nv_bfloat162*)hi)[i * 2 + 1] = H1;
    __nv_bfloat162 L0 = __halves2bfloat162(
        __float2bfloat16(a.x - __bfloat162float(h0)),
        __float2bfloat16(a.y - __bfloat162float(h1)));
    __nv_bfloat162 L1 = __halves2bfloat162(
        __float2bfloat16(a.z - __bfloat162float(h2)),
        __float2bfloat16(a.w - __bfloat162float(h3)));
    ((__nv_bfloat162*)lo)[i * 2 + 0] = L0;
    ((__nv_bfloat162*)lo)[i * 2 + 1] = L1;
}

// ===========================================================================
// Weight transpose + split: out[n][k] = split(W[k][n]); 4 matrices via z
// ===========================================================================
__global__ __launch_bounds__(256) void transpose_split(
    const float* __restrict__ s0, const float* __restrict__ s1,
    const float* __restrict__ s2, const float* __restrict__ s3,
    __nv_bfloat16* __restrict__ bh, __nv_bfloat16* __restrict__ bl)
{
    __shared__ float t[32][33];
    const float* S = blockIdx.z == 0 ? s0 : blockIdx.z == 1 ? s1
                   : blockIdx.z == 2 ? s2 : s3;
    __nv_bfloat16* H = bh + (size_t)blockIdx.z * DM * DM;
    __nv_bfloat16* L = bl + (size_t)blockIdx.z * DM * DM;
    const int x = blockIdx.x * 32, y = blockIdx.y * 32;
    const int tx = threadIdx.x & 31, ty = threadIdx.x >> 5;
#pragma unroll
    for (int i = 0; i < 32; i += 8)
        t[ty + i][tx] = S[(size_t)(y + ty + i) * DM + x + tx];
    __syncthreads();
#pragma unroll
    for (int i = 0; i < 32; i += 8) {
        float a = t[tx][ty + i];
        __nv_bfloat16 h = __float2bfloat16(a);
        size_t idx = (size_t)(x + ty + i) * DM + y + tx;
        H[idx] = h;
        L[idx] = __float2bfloat16(a - __bfloat162float(h));
    }
}

// ===========================================================================
// bf16x3 GEMM via mma.sync: C[M,N] = A[M,K] @ W[K,N], operands pre-split,
// B pre-transposed to [N,K]. CTA tile 128x64, 8 warps of 32x32, K-chunk 32,
// 3-stage cp.async pipeline. M=4096, N=1024, K=1024.
// ===========================================================================
#define GK 1024
#define NCH 32                 // 1024 / 32
#define STG 24576              // A(hi+lo) 16KB + B(hi+lo) 8KB
#define SMEM_GEMM (3 * STG)    // 73728

__global__ __launch_bounds__(256) void gemm_bf16x3(
    const __nv_bfloat16* __restrict__ Ah, const __nv_bfloat16* __restrict__ Al,
    const __nv_bfloat16* __restrict__ Bh, const __nv_bfloat16* __restrict__ Bl,
    float* __restrict__ C)
{
    extern __shared__ char smem[];
    const uint32_t sb = smem_to_u32(smem);
    const int tid = threadIdx.x;
    const int wid = tid >> 5, lane = tid & 31;
    const int wm = wid >> 1, wn = wid & 1;          // 4 x 2 warp grid
    const int r0 = blockIdx.y * 128, c0 = blockIdx.x * 64;

    const char* AgH = (const char*)(Ah + (size_t)r0 * GK);
    const char* AgL = (const char*)(Al + (size_t)r0 * GK);
    const char* BgH = (const char*)(Bh + (size_t)c0 * GK);
    const char* BgL = (const char*)(Bl + (size_t)c0 * GK);

    // smem row: 32 bf16 = 64B = 4 chunks of 16B; swizzle chunk ^ ((row>>1)&3)
    auto load_stage = [&](int st, int ck) {
        const uint32_t sA = sb + st * STG;
        const uint32_t sB = sA + 16384;
        const size_t gofs = (size_t)ck * 64;  // 32 bf16 = 64B along K
        {   // A hi/lo: 128 rows x 4 chunks = 512 chunks each
            int idx0 = tid, idx1 = tid + 256;
            int rA0 = idx0 >> 2, cA0 = idx0 & 3;
            int rA1 = idx1 >> 2, cA1 = idx1 & 3;
            uint32_t o0 = rA0 * 64 + ((cA0 ^ ((rA0 >> 1) & 3)) << 4);
            uint32_t o1 = rA1 * 64 + ((cA1 ^ ((rA1 >> 1) & 3)) << 4);
            CP_ASYNC16(sA + o0, AgH + (size_t)rA0 * 2048 + gofs + cA0 * 16);
            CP_ASYNC16(sA + o1, AgH + (size_t)rA1 * 2048 + gofs + cA1 * 16);
            CP_ASYNC16(sA + 8192 + o0, AgL + (size_t)rA0 * 2048 + gofs + cA0 * 16);
            CP_ASYNC16(sA + 8192 + o1, AgL + (size_t)rA1 * 2048 + gofs + cA1 * 16);
        }
        {   // B hi/lo: 64 rows x 4 chunks = 256 chunks each
            int rB = tid >> 2, cB = tid & 3;
            uint32_t oB = rB * 64 + ((cB ^ ((rB >> 1) & 3)) << 4);
            CP_ASYNC16(sB + oB, BgH + (size_t)rB * 2048 + gofs + cB * 16);
            CP_ASYNC16(sB + 4096 + oB, BgL + (size_t)rB * 2048 + gofs + cB * 16);
        }
    };

    load_stage(0, 0); CP_ASYNC_COMMIT();
    load_stage(1, 1); CP_ASYNC_COMMIT();

    float acc[2][4][4];
#pragma unroll
    for (int mt = 0; mt < 2; ++mt)
#pragma unroll
        for (int nt = 0; nt < 4; ++nt)
#pragma unroll
            for (int r = 0; r < 4; ++r) acc[mt][nt][r] = 0.f;

    const int sub = lane >> 3, l7 = lane & 7;

    for (int i = 0; i < NCH; ++i) {
        if (i + 2 < NCH) load_stage((i + 2) % 3, i + 2);
        CP_ASYNC_COMMIT();
        CP_ASYNC_WAIT2();
        __syncthreads();

        const uint32_t sA = sb + (i % 3) * STG;
        const uint32_t sB = sA + 16384;

#pragma unroll
        for (int ks = 0; ks < 2; ++ks) {
            uint32_t ah[2][4], al[2][4], bh[4][2], bl[4][2];
#pragma unroll
            for (int mt = 0; mt < 2; ++mt) {
                int row = wm * 32 + mt * 16 + ((sub & 1) << 3) + l7;
                int ch = 2 * ks + (sub >> 1);
                uint32_t off = row * 64 + ((ch ^ ((row >> 1) & 3)) << 4);
                LDSM4(ah[mt][0], ah[mt][1], ah[mt][2], ah[mt][3], sA + off);
                LDSM4(al[mt][0], al[mt][1], al[mt][2], al[mt][3], sA + 8192 + off);
            }
#pragma unroll
            for (int p = 0; p < 2; ++p) {
                int row = wn * 32 + p * 16 + ((sub >> 1) << 3) + l7;
                int ch = 2 * ks + (sub & 1);
                uint32_t off = row * 64 + ((ch ^ ((row >> 1) & 3)) << 4);
                LDSM4(bh[2 * p][0], bh[2 * p][1], bh[2 * p + 1][0], bh[2 * p + 1][1],
                      sB + off);
                LDSM4(bl[2 * p][0], bl[2 * p][1], bl[2 * p + 1][0], bl[2 * p + 1][1],
                      sB + 4096 + off);
            }
#pragma unroll
            for (int mt = 0; mt < 2; ++mt)
#pragma unroll
                for (int nt = 0; nt < 4; ++nt) {
                    MMA_BF16(acc[mt][nt], ah[mt], bh[nt]);
                    MMA_BF16(acc[mt][nt], ah[mt], bl[nt]);
                    MMA_BF16(acc[mt][nt], al[mt], bh[nt]);
                }
        }
        __syncthreads();
    }

    // epilogue: fragment -> global f32
#pragma unroll
    for (int mt = 0; mt < 2; ++mt)
#pragma unroll
        for (int nt = 0; nt < 4; ++nt) {
            int row = r0 + wm * 32 + mt * 16 + (lane >> 2);
            int col = c0 + wn * 32 + nt * 8 + 2 * (lane & 3);
            *(float2*)(C + (size_t)row * DM + col) =
                make_float2(acc[mt][nt][0], acc[mt][nt][1]);
            *(float2*)(C + (size_t)(row + 8) * DM + col) =
                make_float2(acc[mt][nt][2], acc[mt][nt][3]);
        }
}

// ===========================================================================
// Fused rel-attention (unchanged from R1)
// ===========================================================================
__global__ __launch_bounds__(256) void attn_kernel(
    const float* __restrict__ qh, const float* __restrict__ kh,
    const float* __restrict__ vh, const float* __restrict__ remb,
    const float* __restrict__ rwb, const float* __restrict__ rbias,
    float* __restrict__ av)
{
    extern __shared__ float smf[];
    float* sq   = smf;
    float* sc   = smf + 64 * 68;
    float* sv   = sc + 64 * 68;
    float* ts   = sv + 64 * 64;
    float* rwbs = ts + 64;

    const int tid = threadIdx.x;
    const int qt = blockIdx.x, n = blockIdx.y, b = blockIdx.z;
    const int i0 = qt * 64;

    if (tid < 64) rwbs[tid] = rwb[n * DH + tid];

    const int lr = tid >> 2;
    const int lc = (tid & 3) << 2;

    {
        const float* qp = qh + (size_t)(b * QL + i0 + lr) * DM + n * DH + lc;
#pragma unroll
        for (int c = 0; c < 64; c += 16) {
            float4 q4 = *(const float4*)(qp + c);
            sq[(lc + c + 0) * 68 + lr] = q4.x;
            sq[(lc + c + 1) * 68 + lr] = q4.y;
            sq[(lc + c + 2) * 68 + lr] = q4.z;
            sq[(lc + c + 3) * 68 + lr] = q4.w;
        }
    }

    const int tx = tid & 15, ty = tid >> 4;
    float o[4][4];
    float rm[4], rl[4];
#pragma unroll
    for (int i = 0; i < 4; ++i) {
        rm[i] = -1e30f; rl[i] = 0.f;
#pragma unroll
        for (int j = 0; j < 4; ++j) o[i][j] = 0.f;
    }

    for (int jt = 0; jt < 16; ++jt) {
        const int j0 = jt * 64;
        __syncthreads();
        {
            const int gj = j0 + lr;
            const float* kp = kh + (size_t)(b * QL + gj) * DM + n * DH + lc;
            const float* vp = vh + (size_t)(b * QL + gj) * DM + n * DH + lc;
            const bool has = (gj + 1 < QL);
            const float* rp = remb + ((size_t)(gj + 1) * NHEAD + n) * DH + lc;
            float tp = 0.f;
#pragma unroll
            for (int c = 0; c < 64; c += 16) {
                float4 k4 = *(const float4*)(kp + c);
                float4 v4 = *(const float4*)(vp + c);
                float4 r4 = has ? *(const float4*)(rp + c)
                                : make_float4(0.f, 0.f, 0.f, 0.f);
                sc[(lc + c + 0) * 68 + lr] = k4.x + r4.x;
                sc[(lc + c + 1) * 68 + lr] = k4.y + r4.y;
                sc[(lc + c + 2) * 68 + lr] = k4.z + r4.z;
                sc[(lc + c + 3) * 68 + lr] = k4.w + r4.w;
                *(float4*)&sv[lr * 64 + lc + c] = v4;
                tp += k4.x * rwbs[lc + c + 0] + k4.y * rwbs[lc + c + 1] +
                      k4.z * rwbs[lc + c + 2] + k4.w * rwbs[lc + c + 3];
            }
            tp += __shfl_xor_sync(0xffffffffu, tp, 1);
            tp += __shfl_xor_sync(0xffffffffu, tp, 2);
            if ((tid & 3) == 0)
                ts[lr] = tp + (has ? rbias[(size_t)(gj + 1) * NHEAD + n] : 0.f);
        }
        __syncthreads();

        float s[4][4];
#pragma unroll
        for (int i = 0; i < 4; ++i)
#pragma unroll
            for (int j = 0; j < 4; ++j) s[i][j] = 0.f;

#pragma unroll 4
        for (int d = 0; d < 64; ++d) {
            float4 a4 = *(const float4*)&sq[d * 68 + 4 * ty];
            float4 b4 = *(const float4*)&sc[d * 68 + 4 * tx];
            float a[4] = {a4.x, a4.y, a4.z, a4.w};
            float bv[4] = {b4.x, b4.y, b4.z, b4.w};
#pragma unroll
            for (int i = 0; i < 4; ++i)
#pragma unroll
                for (int j = 0; j < 4; ++j) s[i][j] += a[i] * bv[j];
        }

#pragma unroll
        for (int i = 0; i < 4; ++i)
#pragma unroll
            for (int j = 0; j < 4; ++j)
                s[i][j] = (s[i][j] + ts[4 * tx + j]) * 0.125f;

        __syncthreads();

#pragma unroll
        for (int i = 0; i < 4; ++i) {
            float mx = fmaxf(fmaxf(s[i][0], s[i][1]), fmaxf(s[i][2], s[i][3]));
            mx = fmaxf(mx, __shfl_xor_sync(0xffffffffu, mx, 1));
            mx = fmaxf(mx, __shfl_xor_sync(0xffffffffu, mx, 2));
            mx = fmaxf(mx, __shfl_xor_sync(0xffffffffu, mx, 4));
            mx = fmaxf(mx, __shfl_xor_sync(0xffffffffu, mx, 8));
            const float mnew = fmaxf(rm[i], mx);
            const float alpha = __expf(rm[i] - mnew);
            rm[i] = mnew;
            float sum = 0.f;
#pragma unroll
            for (int j = 0; j < 4; ++j) {
                const float p = __expf(s[i][j] - mnew);
                sum += p;
                sc[(4 * ty + i) * 68 + 4 * tx + j] = p;
            }
            sum += __shfl_xor_sync(0xffffffffu, sum, 1);
            sum += __shfl_xor_sync(0xffffffffu, sum, 2);
            sum += __shfl_xor_sync(0xffffffffu, sum, 4);
            sum += __shfl_xor_sync(0xffffffffu, sum, 8);
            rl[i] = rl[i] * alpha + sum;
#pragma unroll
            for (int j = 0; j < 4; ++j) o[i][j] *= alpha;
        }
        __syncthreads();

#pragma unroll 4
        for (int j = 0; j < 64; ++j) {
            float4 v4 = *(const float4*)&sv[j * 64 + 4 * tx];
#pragma unroll
            for (int i = 0; i < 4; ++i) {
                const float p = sc[(4 * ty + i) * 68 + j];
                o[i][0] += p * v4.x;
                o[i][1] += p * v4.y;
                o[i][2] += p * v4.z;
                o[i][3] += p * v4.w;
            }
        }
    }

#pragma unroll
    for (int i = 0; i < 4; ++i) {
        const float inv = 1.f / rl[i];
        float4 r = make_float4(o[i][0] * inv, o[i][1] * inv,
                               o[i][2] * inv, o[i][3] * inv);
        *(float4*)&av[(size_t)(b * QL + i0 + 4 * ty + i) * DM + n * DH + 4 * tx] = r;
    }
}

// ===========================================================================
// Residual + LayerNorm (unchanged)
// ===========================================================================
__global__ __launch_bounds__(256) void ln_kernel(
    const float* __restrict__ w, const float* __restrict__ ao,
    const float* __restrict__ gamma, const float* __restrict__ beta,
    float* __restrict__ out)
{
    __shared__ float ssum[8], ssq[8];
    const int row = blockIdx.x;
    const int tid = threadIdx.x;
    const size_t base = (size_t)row * DM + tid * 4;

    float4 x = *(const float4*)(w + base);
    float4 a = *(const float4*)(ao + base);
    x.x += a.x; x.y += a.y; x.z += a.z; x.w += a.w;

    float sum = x.x + x.y + x.z + x.w;
    float sq = x.x * x.x + x.y * x.y + x.z * x.z + x.w * x.w;
#pragma unroll
    for (int off = 16; off; off >>= 1) {
        sum += __shfl_xor_sync(0xffffffffu, sum, off);
        sq += __shfl_xor_sync(0xffffffffu, sq, off);
    }
    const int wid = tid >> 5;
    if ((tid & 31) == 0) { ssum[wid] = sum; ssq[wid] = sq; }
    __syncthreads();
    sum = 0.f; sq = 0.f;
#pragma unroll
    for (int i = 0; i < 8; ++i) { sum += ssum[i]; sq += ssq[i]; }

    const float mu = sum * (1.f / DM);
    const float var = sq * (1.f / DM) - mu * mu;
    const float inv = rsqrtf(var + 1e-5f);

    float4 g = *(const float4*)(gamma + (size_t)tid * 4);
    float4 be = *(const float4*)(beta + (size_t)tid * 4);
    float4 r;
    r.x = (x.x - mu) * inv * g.x + be.x;
    r.y = (x.y - mu) * inv * g.y + be.y;
    r.z = (x.z - mu) * inv * g.z + be.z;
    r.w = (x.w - mu) * inv * g.w + be.w;
    *(float4*)(out + base) = r;
}

// ===========================================================================
extern "C" void kernel_launch(void* const* d_in, const int* in_sizes, int n_in,
                              void* d_out, int out_size)
{
    (void)in_sizes; (void)n_in; (void)out_size;
    const float* w      = (const float*)d_in[0];
    const float* r_emb  = (const float*)d_in[1];
    const float* r_w_b  = (const float*)d_in[2];
    const float* r_bias = (const float*)d_in[3];
    const float* Wq     = (const float*)d_in[4];
    const float* Wk     = (const float*)d_in[5];
    const float* Wv     = (const float*)d_in[6];
    const float* Wo     = (const float*)d_in[7];
    const float* gamma  = (const float*)d_in[8];
    const float* beta   = (const float*)d_in[9];
    float* out = (float*)d_out;

    float *qh, *kh, *vh, *av, *ao;
    __nv_bfloat16 *wh, *wl, *avh, *avl, *bh, *bl;
    cudaGetSymbolAddress((void**)&qh, g_qh);
    cudaGetSymbolAddress((void**)&kh, g_kh);
    cudaGetSymbolAddress((void**)&vh, g_vh);
    cudaGetSymbolAddress((void**)&av, g_av);
    cudaGetSymbolAddress((void**)&ao, g_ao);
    cudaGetSymbolAddress((void**)&wh, g_wh);
    cudaGetSymbolAddress((void**)&wl, g_wl);
    cudaGetSymbolAddress((void**)&avh, g_avh);
    cudaGetSymbolAddress((void**)&avl, g_avl);
    cudaGetSymbolAddress((void**)&bh, g_bh);
    cudaGetSymbolAddress((void**)&bl, g_bl);

    const int n4 = MTOT * DM / 4;
    split_act<<<(n4 + 255) / 256, 256>>>(w, wh, wl, n4);
    transpose_split<<<dim3(32, 32, 4), 256>>>(Wq, Wk, Wv, Wo, bh, bl);

    cudaFuncSetAttribute(gemm_bf16x3,
                         cudaFuncAttributeMaxDynamicSharedMemorySize, SMEM_GEMM);
    dim3 gg(DM / 64, MTOT / 128);  // (16, 32)
    gemm_bf16x3<<<gg, 256, SMEM_GEMM>>>(wh, wl, bh + 0 * (size_t)DM * DM,
                                        bl + 0 * (size_t)DM * DM, qh);
    gemm_bf16x3<<<gg, 256, SMEM_GEMM>>>(wh, wl, bh + 1 * (size_t)DM * DM,
                                        bl + 1 * (size_t)DM * DM, kh);
    gemm_bf16x3<<<gg, 256, SMEM_GEMM>>>(wh, wl, bh + 2 * (size_t)DM * DM,
                                        bl + 2 * (size_t)DM * DM, vh);

    const int smem_attn = (64 * 68 * 2 + 64 * 64 + 64 + 64) * 4;  // 51712 B
    cudaFuncSetAttribute(attn_kernel,
                         cudaFuncAttributeMaxDynamicSharedMemorySize, smem_attn);
    attn_kernel<<<dim3(QL / 64, NHEAD, BB), 256, smem_attn>>>(
        qh, kh, vh, r_emb, r_w_b, r_bias, av);

    split_act<<<(n4 + 255) / 256, 256>>>(av, avh, avl, n4);
    gemm_bf16x3<<<gg, 256, SMEM_GEMM>>>(avh, avl, bh + 3 * (size_t)DM * DM,
                                        bl + 3 * (size_t)DM * DM, ao);
    ln_kernel<<<MTOT, 256>>>(w, ao, gamma, beta, out);
}

// round 4
// speedup vs baseline: 2.6947x; 1.6887x over previous
#include <cuda_runtime.h>
#include <cuda_bf16.h>
#include <cstdint>

#define BB 4
#define QL 1024
#define DM 1024
#define NHEAD 16
#define DH 64
#define MTOT (BB * QL)  // 4096

// fp32 scratch
__device__ float g_qh[(size_t)MTOT * DM];
__device__ float g_kh[(size_t)MTOT * DM];
__device__ float g_vh[(size_t)MTOT * DM];
__device__ float g_ao[(size_t)MTOT * DM];
// bf16 split operands
__device__ __nv_bfloat16 g_wh[(size_t)MTOT * DM];
__device__ __nv_bfloat16 g_wl[(size_t)MTOT * DM];
__device__ __nv_bfloat16 g_avh[(size_t)MTOT * DM];
__device__ __nv_bfloat16 g_avl[(size_t)MTOT * DM];
__device__ __nv_bfloat16 g_bh[(size_t)4 * DM * DM];
__device__ __nv_bfloat16 g_bl[(size_t)4 * DM * DM];
// attention operands (layout [b][n][j][d])
__device__ __nv_bfloat16 g_qbh[(size_t)MTOT * DM];
__device__ __nv_bfloat16 g_qbl[(size_t)MTOT * DM];
__device__ __nv_bfloat16 g_cbh[(size_t)BB * NHEAD * QL * DH];
__device__ __nv_bfloat16 g_cbl[(size_t)BB * NHEAD * QL * DH];
__device__ __nv_bfloat16 g_vbh[(size_t)BB * NHEAD * QL * DH];
__device__ __nv_bfloat16 g_vbl[(size_t)BB * NHEAD * QL * DH];
__device__ float g_ts[(size_t)BB * NHEAD * QL];

// ===========================================================================
// PTX helpers (portable sm_80/sm_90-class only; NO sm_103a-gated features)
// ===========================================================================
__device__ __forceinline__ uint32_t smem_to_u32(const void* p) {
    uint32_t a;
    asm("{ .reg .u64 t; cvta.to.shared.u64 t, %1; cvt.u32.u64 %0, t; }"
        : "=r"(a) : "l"(p));
    return a;
}
#define CP_ASYNC16(s, g) \
    asm volatile("cp.async.cg.shared.global [%0], [%1], 16;" :: "r"(s), "l"(g) : "memory")
#define CP_ASYNC_COMMIT() asm volatile("cp.async.commit_group;" ::: "memory")
#define CP_ASYNC_WAIT2() asm volatile("cp.async.wait_group 2;" ::: "memory")
#define CP_ASYNC_WAIT1() asm volatile("cp.async.wait_group 1;" ::: "memory")

#define LDSM4(r0, r1, r2, r3, addr)                                            \
    asm volatile("ldmatrix.sync.aligned.m8n8.x4.shared.b16 {%0,%1,%2,%3}, [%4];" \
                 : "=r"(r0), "=r"(r1), "=r"(r2), "=r"(r3) : "r"(addr))
#define LDSM4T(r0, r1, r2, r3, addr)                                           \
    asm volatile("ldmatrix.sync.aligned.m8n8.x4.trans.shared.b16 {%0,%1,%2,%3}, [%4];" \
                 : "=r"(r0), "=r"(r1), "=r"(r2), "=r"(r3) : "r"(addr))

#define MMA_BF16(d, a, b)                                                      \
    asm volatile("mma.sync.aligned.m16n8k16.row.col.f32.bf16.bf16.f32 "        \
                 "{%0,%1,%2,%3}, {%4,%5,%6,%7}, {%8,%9}, {%0,%1,%2,%3};"       \
                 : "+f"((d)[0]), "+f"((d)[1]), "+f"((d)[2]), "+f"((d)[3])      \
                 : "r"((a)[0]), "r"((a)[1]), "r"((a)[2]), "r"((a)[3]),         \
                   "r"((b)[0]), "r"((b)[1]))

// 128B rows, 8x16B chunks, xor-swizzle
#define SWOFF(row, ch) ((row) * 128 + (((ch) ^ ((row) & 7)) << 4))

// ===========================================================================
// Split fp32 -> bf16 hi + lo
// ===========================================================================
__global__ __launch_bounds__(256) void split_act(
    const float* __restrict__ in, __nv_bfloat16* __restrict__ hi,
    __nv_bfloat16* __restrict__ lo, int n4)
{
    int i = blockIdx.x * 256 + threadIdx.x;
    if (i >= n4) return;
    float4 a = ((const float4*)in)[i];
    __nv_bfloat16 h0 = __float2bfloat16(a.x), h1 = __float2bfloat16(a.y);
    __nv_bfloat16 h2 = __float2bfloat16(a.z), h3 = __float2bfloat16(a.w);
    ((__nv_bfloat162*)hi)[i * 2 + 0] = __halves2bfloat162(h0, h1);
    ((__nv_bfloat162*)hi)[i * 2 + 1] = __halves2bfloat162(h2, h3);
    ((__nv_bfloat162*)lo)[i * 2 + 0] = __halves2bfloat162(
        __float2bfloat16(a.x - __bfloat162float(h0)),
        __float2bfloat16(a.y - __bfloat162float(h1)));
    ((__nv_bfloat162*)lo)[i * 2 + 1] = __halves2bfloat162(
        __float2bfloat16(a.z - __bfloat162float(h2)),
        __float2bfloat16(a.w - __bfloat162float(h3)));
}

// ===========================================================================
// Weight transpose + split
// ===========================================================================
__global__ __launch_bounds__(256) void transpose_split(
    const float* __restrict__ s0, const float* __restrict__ s1,
    const float* __restrict__ s2, const float* __restrict__ s3,
    __nv_bfloat16* __restrict__ bh, __nv_bfloat16* __restrict__ bl)
{
    __shared__ float t[32][33];
    const float* S = blockIdx.z == 0 ? s0 : blockIdx.z == 1 ? s1
                   : blockIdx.z == 2 ? s2 : s3;
    __nv_bfloat16* H = bh + (size_t)blockIdx.z * DM * DM;
    __nv_bfloat16* L = bl + (size_t)blockIdx.z * DM * DM;
    const int x = blockIdx.x * 32, y = blockIdx.y * 32;
    const int tx = threadIdx.x & 31, ty = threadIdx.x >> 5;
#pragma unroll
    for (int i = 0; i < 32; i += 8)
        t[ty + i][tx] = S[(size_t)(y + ty + i) * DM + x + tx];
    __syncthreads();
#pragma unroll
    for (int i = 0; i < 32; i += 8) {
        float a = t[tx][ty + i];
        __nv_bfloat16 h = __float2bfloat16(a);
        size_t idx = (size_t)(x + ty + i) * DM + y + tx;
        H[idx] = h;
        L[idx] = __float2bfloat16(a - __bfloat162float(h));
    }
}

// ===========================================================================
// prep_kv: per (b,n,j): C = K + shifted r_emb (split), V split, ts scalar.
// Output layout [b][n][j][d]. One warp per row.
// ===========================================================================
__global__ __launch_bounds__(256) void prep_kv(
    const float* __restrict__ kh, const float* __restrict__ vh,
    const float* __restrict__ remb, const float* __restrict__ rwb,
    const float* __restrict__ rbias,
    __nv_bfloat16* __restrict__ cbh, __nv_bfloat16* __restrict__ cbl,
    __nv_bfloat16* __restrict__ vbh, __nv_bfloat16* __restrict__ vbl,
    float* __restrict__ tsg)
{
    const int gw = (blockIdx.x * 256 + threadIdx.x) >> 5;
    const int lane = threadIdx.x & 31;
    const int b = gw >> 14, n = (gw >> 10) & 15, j = gw & 1023;

    const size_t src = (size_t)(b * QL + j) * DM + n * DH + lane * 2;
    float2 k2 = *(const float2*)(kh + src);
    float2 v2 = *(const float2*)(vh + src);
    const bool has = (j + 1) < QL;
    float2 r2 = make_float2(0.f, 0.f);
    if (has) r2 = *(const float2*)(remb + ((size_t)(j + 1) * NHEAD + n) * DH + lane * 2);
    float2 rw2 = *(const float2*)(rwb + n * DH + lane * 2);

    float cx = k2.x + r2.x, cy = k2.y + r2.y;
    const size_t o = ((size_t)(b * NHEAD + n) * QL + j) * DH + lane * 2;

    __nv_bfloat162 ch2 = __floats2bfloat162_rn(cx, cy);
    *(__nv_bfloat162*)(cbh + o) = ch2;
    *(__nv_bfloat162*)(cbl + o) = __floats2bfloat162_rn(
        cx - __bfloat162float(ch2.x), cy - __bfloat162float(ch2.y));
    __nv_bfloat162 vh2 = __floats2bfloat162_rn(v2.x, v2.y);
    *(__nv_bfloat162*)(vbh + o) = vh2;
    *(__nv_bfloat162*)(vbl + o) = __floats2bfloat162_rn(
        v2.x - __bfloat162float(vh2.x), v2.y - __bfloat162float(vh2.y));

    float dot = rw2.x * k2.x + rw2.y * k2.y;
#pragma unroll
    for (int off = 16; off; off >>= 1)
        dot += __shfl_xor_sync(0xffffffffu, dot, off);
    if (lane == 0)
        tsg[(size_t)(b * NHEAD + n) * QL + j] =
            dot + (has ? rbias[(size_t)(j + 1) * NHEAD + n] : 0.f);
}

// ===========================================================================
// bf16x3 GEMM via mma.sync (unchanged from R3)
// ===========================================================================
#define GK 1024
#define NCH 32
#define STG 24576
#define SMEM_GEMM (3 * STG)

__global__ __launch_bounds__(256) void gemm_bf16x3(
    const __nv_bfloat16* __restrict__ Ah, const __nv_bfloat16* __restrict__ Al,
    const __nv_bfloat16* __restrict__ Bh, const __nv_bfloat16* __restrict__ Bl,
    float* __restrict__ C)
{
    extern __shared__ char smem[];
    const uint32_t sb = smem_to_u32(smem);
    const int tid = threadIdx.x;
    const int wid = tid >> 5, lane = tid & 31;
    const int wm = wid >> 1, wn = wid & 1;
    const int r0 = blockIdx.y * 128, c0 = blockIdx.x * 64;

    const char* AgH = (const char*)(Ah + (size_t)r0 * GK);
    const char* AgL = (const char*)(Al + (size_t)r0 * GK);
    const char* BgH = (const char*)(Bh + (size_t)c0 * GK);
    const char* BgL = (const char*)(Bl + (size_t)c0 * GK);

    auto load_stage = [&](int st, int ck) {
        const uint32_t sA = sb + st * STG;
        const uint32_t sB = sA + 16384;
        const size_t gofs = (size_t)ck * 64;
        {
            int idx0 = tid, idx1 = tid + 256;
            int rA0 = idx0 >> 2, cA0 = idx0 & 3;
            int rA1 = idx1 >> 2, cA1 = idx1 & 3;
            uint32_t o0 = rA0 * 64 + ((cA0 ^ ((rA0 >> 1) & 3)) << 4);
            uint32_t o1 = rA1 * 64 + ((cA1 ^ ((rA1 >> 1) & 3)) << 4);
            CP_ASYNC16(sA + o0, AgH + (size_t)rA0 * 2048 + gofs + cA0 * 16);
            CP_ASYNC16(sA + o1, AgH + (size_t)rA1 * 2048 + gofs + cA1 * 16);
            CP_ASYNC16(sA + 8192 + o0, AgL + (size_t)rA0 * 2048 + gofs + cA0 * 16);
            CP_ASYNC16(sA + 8192 + o1, AgL + (size_t)rA1 * 2048 + gofs + cA1 * 16);
        }
        {
            int rB = tid >> 2, cB = tid & 3;
            uint32_t oB = rB * 64 + ((cB ^ ((rB >> 1) & 3)) << 4);
            CP_ASYNC16(sB + oB, BgH + (size_t)rB * 2048 + gofs + cB * 16);
            CP_ASYNC16(sB + 4096 + oB, BgL + (size_t)rB * 2048 + gofs + cB * 16);
        }
    };

    load_stage(0, 0); CP_ASYNC_COMMIT();
    load_stage(1, 1); CP_ASYNC_COMMIT();

    float acc[2][4][4];
#pragma unroll
    for (int mt = 0; mt < 2; ++mt)
#pragma unroll
        for (int nt = 0; nt < 4; ++nt)
#pragma unroll
            for (int r = 0; r < 4; ++r) acc[mt][nt][r] = 0.f;

    const int sub = lane >> 3, l7 = lane & 7;

    for (int i = 0; i < NCH; ++i) {
        if (i + 2 < NCH) load_stage((i + 2) % 3, i + 2);
        CP_ASYNC_COMMIT();
        CP_ASYNC_WAIT2();
        __syncthreads();

        const uint32_t sA = sb + (i % 3) * STG;
        const uint32_t sB = sA + 16384;

#pragma unroll
        for (int ks = 0; ks < 2; ++ks) {
            uint32_t ah[2][4], al[2][4], bh[4][2], bl[4][2];
#pragma unroll
            for (int mt = 0; mt < 2; ++mt) {
                int row = wm * 32 + mt * 16 + ((sub & 1) << 3) + l7;
                int ch = 2 * ks + (sub >> 1);
                uint32_t off = row * 64 + ((ch ^ ((row >> 1) & 3)) << 4);
                LDSM4(ah[mt][0], ah[mt][1], ah[mt][2], ah[mt][3], sA + off);
                LDSM4(al[mt][0], al[mt][1], al[mt][2], al[mt][3], sA + 8192 + off);
            }
#pragma unroll
            for (int p = 0; p < 2; ++p) {
                int row = wn * 32 + p * 16 + ((sub >> 1) << 3) + l7;
                int ch = 2 * ks + (sub & 1);
                uint32_t off = row * 64 + ((ch ^ ((row >> 1) & 3)) << 4);
                LDSM4(bh[2 * p][0], bh[2 * p][1], bh[2 * p + 1][0], bh[2 * p + 1][1],
                      sB + off);
                LDSM4(bl[2 * p][0], bl[2 * p][1], bl[2 * p + 1][0], bl[2 * p + 1][1],
                      sB + 4096 + off);
            }
#pragma unroll
            for (int mt = 0; mt < 2; ++mt)
#pragma unroll
                for (int nt = 0; nt < 4; ++nt) {
                    MMA_BF16(acc[mt][nt], ah[mt], bh[nt]);
                    MMA_BF16(acc[mt][nt], ah[mt], bl[nt]);
                    MMA_BF16(acc[mt][nt], al[mt], bh[nt]);
                }
        }
        __syncthreads();
    }

#pragma unroll
    for (int mt = 0; mt < 2; ++mt)
#pragma unroll
        for (int nt = 0; nt < 4; ++nt) {
            int row = r0 + wm * 32 + mt * 16 + (lane >> 2);
            int col = c0 + wn * 32 + nt * 8 + 2 * (lane & 3);
            *(float2*)(C + (size_t)row * DM + col) =
                make_float2(acc[mt][nt][0], acc[mt][nt][1]);
            *(float2*)(C + (size_t)(row + 8) * DM + col) =
                make_float2(acc[mt][nt][2], acc[mt][nt][3]);
        }
}

// ===========================================================================
// MMA flash attention. CTA = (64-query tile, head, batch). 4 warps.
// S = Q.C^T (bf16x3), softmax in fragments, O = P.V (bf16x3, P split in regs).
// ===========================================================================
#define ATT_STG 33024                 // Ch|Cl|Vh|Vl (4x8192) + ts 256
#define ATT_SMEM (16384 + 2 * ATT_STG)  // + Q hi/lo

__global__ __launch_bounds__(128) void attn_mma(
    const __nv_bfloat16* __restrict__ qbh, const __nv_bfloat16* __restrict__ qbl,
    const __nv_bfloat16* __restrict__ cbh, const __nv_bfloat16* __restrict__ cbl,
    const __nv_bfloat16* __restrict__ vbh, const __nv_bfloat16* __restrict__ vbl,
    const float* __restrict__ tsg,
    __nv_bfloat16* __restrict__ avh, __nv_bfloat16* __restrict__ avl)
{
    extern __shared__ char sm[];
    const uint32_t sb = smem_to_u32(sm);
    const uint32_t sQh = sb, sQl = sb + 8192;

    const int tid = threadIdx.x;
    const int wid = tid >> 5, lane = tid & 31;
    const int sub = lane >> 3, l7 = lane & 7;
    const int i0 = blockIdx.x * 64, n = blockIdx.y, b = blockIdx.z;

    // ---- Q load (once) ----
    const char* qhg = (const char*)qbh + ((size_t)(b * QL + i0) * DM + n * DH) * 2;
    const char* qlg = (const char*)qbl + ((size_t)(b * QL + i0) * DM + n * DH) * 2;
#pragma unroll
    for (int r = 0; r < 4; ++r) {
        int id = r * 128 + tid;
        int row = id >> 3, ch = id & 7;
        uint32_t o = SWOFF(row, ch);
        CP_ASYNC16(sQh + o, qhg + (size_t)row * 2048 + ch * 16);
        CP_ASYNC16(sQl + o, qlg + (size_t)row * 2048 + ch * 16);
    }
    CP_ASYNC_COMMIT();

    const size_t kvb = ((size_t)(b * NHEAD + n) * QL) * DH * 2;  // bytes
    const char* chg = (const char*)cbh + kvb;
    const char* clg = (const char*)cbl + kvb;
    const char* vhg = (const char*)vbh + kvb;
    const char* vlg = (const char*)vbl + kvb;
    const char* tg = (const char*)(tsg + (size_t)(b * NHEAD + n) * QL);

    auto load_stage = [&](int s, int jt) {
        const uint32_t st = sb + 16384 + s * ATT_STG;
        const size_t go = (size_t)jt * 64 * 128;
#pragma unroll
        for (int r = 0; r < 4; ++r) {
            int id = r * 128 + tid;
            int row = id >> 3, ch = id & 7;
            uint32_t o = SWOFF(row, ch);
            size_t g = go + (size_t)row * 128 + ch * 16;
            CP_ASYNC16(st + o, chg + g);
            CP_ASYNC16(st + 8192 + o, clg + g);
            CP_ASYNC16(st + 16384 + o, vhg + g);
            CP_ASYNC16(st + 24576 + o, vlg + g);
        }
        if (tid < 16) CP_ASYNC16(st + 32768 + tid * 16, tg + (size_t)jt * 256 + tid * 16);
    };

    load_stage(0, 0); CP_ASYNC_COMMIT();
    load_stage(1, 1); CP_ASYNC_COMMIT();

    uint32_t qhf[4][4], qlf[4][4];
    float o_[8][4];
    float m0 = -1e30f, m1 = -1e30f, l0 = 0.f, l1 = 0.f;
#pragma unroll
    for (int t = 0; t < 8; ++t)
#pragma unroll
        for (int r = 0; r < 4; ++r) o_[t][r] = 0.f;

    for (int jt = 0; jt < 16; ++jt) {
        CP_ASYNC_WAIT1();
        __syncthreads();

        if (jt == 0) {
#pragma unroll
            for (int kc = 0; kc < 4; ++kc) {
                int row = wid * 16 + ((sub & 1) << 3) + l7;
                int ch = 2 * kc + (sub >> 1);
                uint32_t o = SWOFF(row, ch);
                LDSM4(qhf[kc][0], qhf[kc][1], qhf[kc][2], qhf[kc][3], sQh + o);
                LDSM4(qlf[kc][0], qlf[kc][1], qlf[kc][2], qlf[kc][3], sQl + o);
            }
        }

        const uint32_t st = sb + 16384 + (jt & 1) * ATT_STG;
        const float* tsp = (const float*)(sm + 16384 + (jt & 1) * ATT_STG + 32768);

        // ---- S = Q . C^T ----
        float s[8][4];
#pragma unroll
        for (int t = 0; t < 8; ++t)
#pragma unroll
            for (int r = 0; r < 4; ++r) s[t][r] = 0.f;

#pragma unroll
        for (int kc = 0; kc < 4; ++kc) {
#pragma unroll
            for (int p = 0; p < 4; ++p) {
                int row = p * 16 + ((sub >> 1) << 3) + l7;
                int ch = 2 * kc + (sub & 1);
                uint32_t o = SWOFF(row, ch);
                uint32_t bh[2][2], bl[2][2];
                LDSM4(bh[0][0], bh[0][1], bh[1][0], bh[1][1], st + o);
                LDSM4(bl[0][0], bl[0][1], bl[1][0], bl[1][1], st + 8192 + o);
#pragma unroll
                for (int h = 0; h < 2; ++h) {
                    MMA_BF16(s[2 * p + h], qhf[kc], bh[h]);
                    MMA_BF16(s[2 * p + h], qhf[kc], bl[h]);
                    MMA_BF16(s[2 * p + h], qlf[kc], bh[h]);
                }
            }
        }

        // ---- bias + scale ----
#pragma unroll
        for (int t = 0; t < 8; ++t) {
            float2 tv = *(const float2*)(tsp + t * 8 + (lane & 3) * 2);
            s[t][0] = (s[t][0] + tv.x) * 0.125f;
            s[t][1] = (s[t][1] + tv.y) * 0.125f;
            s[t][2] = (s[t][2] + tv.x) * 0.125f;
            s[t][3] = (s[t][3] + tv.y) * 0.125f;
        }

        // ---- online softmax ----
        float mx0 = -1e30f, mx1 = -1e30f;
#pragma unroll
        for (int t = 0; t < 8; ++t) {
            mx0 = fmaxf(mx0, fmaxf(s[t][0], s[t][1]));
            mx1 = fmaxf(mx1, fmaxf(s[t][2], s[t][3]));
        }
        mx0 = fmaxf(mx0, __shfl_xor_sync(0xffffffffu, mx0, 1));
        mx0 = fmaxf(mx0, __shfl_xor_sync(0xffffffffu, mx0, 2));
        mx1 = fmaxf(mx1, __shfl_xor_sync(0xffffffffu, mx1, 1));
        mx1 = fmaxf(mx1, __shfl_xor_sync(0xffffffffu, mx1, 2));
        const float nm0 = fmaxf(m0, mx0), nm1 = fmaxf(m1, mx1);
        const float a0 = __expf(m0 - nm0), a1 = __expf(m1 - nm1);
        m0 = nm0; m1 = nm1;

        float sum0 = 0.f, sum1 = 0.f;
#pragma unroll
        for (int t = 0; t < 8; ++t) {
            s[t][0] = __expf(s[t][0] - nm0);
            s[t][1] = __expf(s[t][1] - nm0);
            s[t][2] = __expf(s[t][2] - nm1);
            s[t][3] = __expf(s[t][3] - nm1);
            sum0 += s[t][0] + s[t][1];
            sum1 += s[t][2] + s[t][3];
        }
        sum0 += __shfl_xor_sync(0xffffffffu, sum0, 1);
        sum0 += __shfl_xor_sync(0xffffffffu, sum0, 2);
        sum1 += __shfl_xor_sync(0xffffffffu, sum1, 1);
        sum1 += __shfl_xor_sync(0xffffffffu, sum1, 2);
        l0 = l0 * a0 + sum0;
        l1 = l1 * a1 + sum1;
#pragma unroll
        for (int t = 0; t < 8; ++t) {
            o_[t][0] *= a0; o_[t][1] *= a0;
            o_[t][2] *= a1; o_[t][3] *= a1;
        }

        // ---- O += P . V ----
#pragma unroll
        for (int kc = 0; kc < 4; ++kc) {
            uint32_t ah[4], al[4];
#pragma unroll
            for (int h = 0; h < 2; ++h) {
                const int t = 2 * kc + h;
                __nv_bfloat162 p01 = __floats2bfloat162_rn(s[t][0], s[t][1]);
                __nv_bfloat162 p23 = __floats2bfloat162_rn(s[t][2], s[t][3]);
                ah[2 * h + 0] = *(uint32_t*)&p01;
                ah[2 * h + 1] = *(uint32_t*)&p23;
                __nv_bfloat162 q01 = __floats2bfloat162_rn(
                    s[t][0] - __bfloat162float(p01.x),
                    s[t][1] - __bfloat162float(p01.y));
                __nv_bfloat162 q23 = __floats2bfloat162_rn(
                    s[t][2] - __bfloat162float(p23.x),
                    s[t][3] - __bfloat162float(p23.y));
                al[2 * h + 0] = *(uint32_t*)&q01;
                al[2 * h + 1] = *(uint32_t*)&q23;
            }
            // hmm: A frag order must be a0=(r,k),a1=(r+8,k),a2=(r,k+8),a3=(r+8,k+8)
            // p01 of t=2kc -> (r,k); p23 of t=2kc -> (r+8,k); p01 of t=2kc+1 -> (r,k+8)
            // (mapping above already produces this order: h=0 fills a0,a1; h=1 fills a2,a3)
#pragma unroll
            for (int g = 0; g < 4; ++g) {
                int row = 16 * kc + ((sub & 1) << 3) + l7;
                int ch = 2 * g + (sub >> 1);
                uint32_t o = SWOFF(row, ch);
                uint32_t vh[2][2], vl[2][2];
                LDSM4T(vh[0][0], vh[0][1], vh[1][0], vh[1][1], st + 16384 + o);
                LDSM4T(vl[0][0], vl[0][1], vl[1][0], vl[1][1], st + 24576 + o);
#pragma unroll
                for (int h = 0; h < 2; ++h) {
                    MMA_BF16(o_[2 * g + h], ah, vh[h]);
                    MMA_BF16(o_[2 * g + h], ah, vl[h]);
                    MMA_BF16(o_[2 * g + h], al, vh[h]);
                }
            }
        }

        __syncthreads();
        if (jt + 2 < 16) load_stage(jt & 1, jt + 2);
        CP_ASYNC_COMMIT();
    }

    // ---- normalize + store bf16 hi/lo ----
    const float inv0 = 1.f / l0, inv1 = 1.f / l1;
    const int row0 = i0 + wid * 16 + (lane >> 2);
#pragma unroll
    for (int t = 0; t < 8; ++t) {
        const int col = n * DH + t * 8 + (lane & 3) * 2;
        float v0 = o_[t][0] * inv0, v1 = o_[t][1] * inv0;
        float v2 = o_[t][2] * inv1, v3 = o_[t][3] * inv1;
        __nv_bfloat162 h01 = __floats2bfloat162_rn(v0, v1);
        __nv_bfloat162 h23 = __floats2bfloat162_rn(v2, v3);
        size_t p0 = (size_t)(b * QL + row0) * DM + col;
        size_t p1 = (size_t)(b * QL + row0 + 8) * DM + col;
        *(__nv_bfloat162*)(avh + p0) = h01;
        *(__nv_bfloat162*)(avh + p1) = h23;
        *(__nv_bfloat162*)(avl + p0) = __floats2bfloat162_rn(
            v0 - __bfloat162float(h01.x), v1 - __bfloat162float(h01.y));
        *(__nv_bfloat162*)(avl + p1) = __floats2bfloat162_rn(
            v2 - __bfloat162float(h23.x), v3 - __bfloat162float(h23.y));
    }
}

// ===========================================================================
// Residual + LayerNorm (unchanged)
// ===========================================================================
__global__ __launch_bounds__(256) void ln_kernel(
    const float* __restrict__ w, const float* __restrict__ ao,
    const float* __restrict__ gamma, const float* __restrict__ beta,
    float* __restrict__ out)
{
    __shared__ float ssum[8], ssq[8];
    const int row = blockIdx.x;
    const int tid = threadIdx.x;
    const size_t base = (size_t)row * DM + tid * 4;

    float4 x = *(const float4*)(w + base);
    float4 a = *(const float4*)(ao + base);
    x.x += a.x; x.y += a.y; x.z += a.z; x.w += a.w;

    float sum = x.x + x.y + x.z + x.w;
    float sq = x.x * x.x + x.y * x.y + x.z * x.z + x.w * x.w;
#pragma unroll
    for (int off = 16; off; off >>= 1) {
        sum += __shfl_xor_sync(0xffffffffu, sum, off);
        sq += __shfl_xor_sync(0xffffffffu, sq, off);
    }
    const int wid = tid >> 5;
    if ((tid & 31) == 0) { ssum[wid] = sum; ssq[wid] = sq; }
    __syncthreads();
    sum = 0.f; sq = 0.f;
#pragma unroll
    for (int i = 0; i < 8; ++i) { sum += ssum[i]; sq += ssq[i]; }

    const float mu = sum * (1.f / DM);
    const float var = sq * (1.f / DM) - mu * mu;
    const float inv = rsqrtf(var + 1e-5f);

    float4 g = *(const float4*)(gamma + (size_t)tid * 4);
    float4 be = *(const float4*)(beta + (size_t)tid * 4);
    float4 r;
    r.x = (x.x - mu) * inv * g.x + be.x;
    r.y = (x.y - mu) * inv * g.y + be.y;
    r.z = (x.z - mu) * inv * g.z + be.z;
    r.w = (x.w - mu) * inv * g.w + be.w;
    *(float4*)(out + base) = r;
}

// ===========================================================================
extern "C" void kernel_launch(void* const* d_in, const int* in_sizes, int n_in,
                              void* d_out, int out_size)
{
    (void)in_sizes; (void)n_in; (void)out_size;
    const float* w      = (const float*)d_in[0];
    const float* r_emb  = (const float*)d_in[1];
    const float* r_w_b  = (const float*)d_in[2];
    const float* r_bias = (const float*)d_in[3];
    const float* Wq     = (const float*)d_in[4];
    const float* Wk     = (const float*)d_in[5];
    const float* Wv     = (const float*)d_in[6];
    const float* Wo     = (const float*)d_in[7];
    const float* gamma  = (const float*)d_in[8];
    const float* beta   = (const float*)d_in[9];
    float* out = (float*)d_out;

    float *qh, *kh, *vh, *ao, *tsg;
    __nv_bfloat16 *wh, *wl, *avh, *avl, *bh, *bl;
    __nv_bfloat16 *qbh, *qbl, *cbh, *cbl, *vbh, *vbl;
    cudaGetSymbolAddress((void**)&qh, g_qh);
    cudaGetSymbolAddress((void**)&kh, g_kh);
    cudaGetSymbolAddress((void**)&vh, g_vh);
    cudaGetSymbolAddress((void**)&ao, g_ao);
    cudaGetSymbolAddress((void**)&wh, g_wh);
    cudaGetSymbolAddress((void**)&wl, g_wl);
    cudaGetSymbolAddress((void**)&avh, g_avh);
    cudaGetSymbolAddress((void**)&avl, g_avl);
    cudaGetSymbolAddress((void**)&bh, g_bh);
    cudaGetSymbolAddress((void**)&bl, g_bl);
    cudaGetSymbolAddress((void**)&qbh, g_qbh);
    cudaGetSymbolAddress((void**)&qbl, g_qbl);
    cudaGetSymbolAddress((void**)&cbh, g_cbh);
    cudaGetSymbolAddress((void**)&cbl, g_cbl);
    cudaGetSymbolAddress((void**)&vbh, g_vbh);
    cudaGetSymbolAddress((void**)&vbl, g_vbl);
    cudaGetSymbolAddress((void**)&tsg, g_ts);

    const int n4 = MTOT * DM / 4;
    split_act<<<(n4 + 255) / 256, 256>>>(w, wh, wl, n4);
    transpose_split<<<dim3(32, 32, 4), 256>>>(Wq, Wk, Wv, Wo, bh, bl);

    cudaFuncSetAttribute(gemm_bf16x3,
                         cudaFuncAttributeMaxDynamicSharedMemorySize, SMEM_GEMM);
    dim3 gg(DM / 64, MTOT / 128);
    gemm_bf16x3<<<gg, 256, SMEM_GEMM>>>(wh, wl, bh + 0 * (size_t)DM * DM,
                                        bl + 0 * (size_t)DM * DM, qh);
    gemm_bf16x3<<<gg, 256, SMEM_GEMM>>>(wh, wl, bh + 1 * (size_t)DM * DM,
                                        bl + 1 * (size_t)DM * DM, kh);
    gemm_bf16x3<<<gg, 256, SMEM_GEMM>>>(wh, wl, bh + 2 * (size_t)DM * DM,
                                        bl + 2 * (size_t)DM * DM, vh);

    split_act<<<(n4 + 255) / 256, 256>>>(qh, qbh, qbl, n4);
    prep_kv<<<(BB * NHEAD * QL) / 8, 256>>>(kh, vh, r_emb, r_w_b, r_bias,
                                            cbh, cbl, vbh, vbl, tsg);

    cudaFuncSetAttribute(attn_mma,
                         cudaFuncAttributeMaxDynamicSharedMemorySize, ATT_SMEM);
    attn_mma<<<dim3(QL / 64, NHEAD, BB), 128, ATT_SMEM>>>(
        qbh, qbl, cbh, cbl, vbh, vbl, tsg, avh, avl);

    gemm_bf16x3<<<gg, 256, SMEM_GEMM>>>(avh, avl, bh + 3 * (size_t)DM * DM,
                                        bl + 3 * (size_t)DM * DM, ao);
    ln_kernel<<<MTOT, 256>>>(w, ao, gamma, beta, out);
}

// round 5
// speedup vs baseline: 2.9598x; 1.0984x over previous
#include <cuda_runtime.h>
#include <cuda_bf16.h>
#include <cstdint>

#define BB 4
#define QL 1024
#define DM 1024
#define NHEAD 16
#define DH 64
#define MTOT (BB * QL)  // 4096

// fp32 scratch
__device__ float g_kh[(size_t)MTOT * DM];
__device__ float g_vh[(size_t)MTOT * DM];
__device__ float g_ao[(size_t)MTOT * DM];
// bf16 split operands
__device__ __nv_bfloat16 g_wh[(size_t)MTOT * DM];
__device__ __nv_bfloat16 g_wl[(size_t)MTOT * DM];
__device__ __nv_bfloat16 g_avh[(size_t)MTOT * DM];
__device__ __nv_bfloat16 g_avl[(size_t)MTOT * DM];
__device__ __nv_bfloat16 g_bh[(size_t)4 * DM * DM];
__device__ __nv_bfloat16 g_bl[(size_t)4 * DM * DM];
// attention operands
__device__ __nv_bfloat16 g_qbh[(size_t)MTOT * DM];
__device__ __nv_bfloat16 g_qbl[(size_t)MTOT * DM];
__device__ __nv_bfloat16 g_cbh[(size_t)BB * NHEAD * QL * DH];
__device__ __nv_bfloat16 g_cbl[(size_t)BB * NHEAD * QL * DH];
__device__ __nv_bfloat16 g_vbh[(size_t)BB * NHEAD * QL * DH];
__device__ __nv_bfloat16 g_vbl[(size_t)BB * NHEAD * QL * DH];
__device__ float g_ts[(size_t)BB * NHEAD * QL];

// ===========================================================================
// PTX helpers (portable sm_80/90-class only)
// ===========================================================================
__device__ __forceinline__ uint32_t smem_to_u32(const void* p) {
    uint32_t a;
    asm("{ .reg .u64 t; cvta.to.shared.u64 t, %1; cvt.u32.u64 %0, t; }"
        : "=r"(a) : "l"(p));
    return a;
}
#define CP_ASYNC16(s, g) \
    asm volatile("cp.async.cg.shared.global [%0], [%1], 16;" :: "r"(s), "l"(g) : "memory")
#define CP_ASYNC_COMMIT() asm volatile("cp.async.commit_group;" ::: "memory")
#define CP_ASYNC_WAIT2() asm volatile("cp.async.wait_group 2;" ::: "memory")
#define CP_ASYNC_WAIT1() asm volatile("cp.async.wait_group 1;" ::: "memory")

#define LDSM4(r0, r1, r2, r3, addr)                                            \
    asm volatile("ldmatrix.sync.aligned.m8n8.x4.shared.b16 {%0,%1,%2,%3}, [%4];" \
                 : "=r"(r0), "=r"(r1), "=r"(r2), "=r"(r3) : "r"(addr))
#define LDSM4T(r0, r1, r2, r3, addr)                                           \
    asm volatile("ldmatrix.sync.aligned.m8n8.x4.trans.shared.b16 {%0,%1,%2,%3}, [%4];" \
                 : "=r"(r0), "=r"(r1), "=r"(r2), "=r"(r3) : "r"(addr))

#define MMA_BF16(d, a, b)                                                      \
    asm volatile("mma.sync.aligned.m16n8k16.row.col.f32.bf16.bf16.f32 "        \
                 "{%0,%1,%2,%3}, {%4,%5,%6,%7}, {%8,%9}, {%0,%1,%2,%3};"       \
                 : "+f"((d)[0]), "+f"((d)[1]), "+f"((d)[2]), "+f"((d)[3])      \
                 : "r"((a)[0]), "r"((a)[1]), "r"((a)[2]), "r"((a)[3]),         \
                   "r"((b)[0]), "r"((b)[1]))

// 64B rows (32 bf16), 4x16B chunks
#define SW64(row, ch) ((row) * 64 + (((ch) ^ (((row) >> 1) & 3)) << 4))
// 128B rows (64 bf16), 8x16B chunks
#define SWOFF(row, ch) ((row) * 128 + (((ch) ^ ((row) & 7)) << 4))

// ===========================================================================
// Split fp32 -> bf16 hi + lo
// ===========================================================================
__global__ __launch_bounds__(256) void split_act(
    const float* __restrict__ in, __nv_bfloat16* __restrict__ hi,
    __nv_bfloat16* __restrict__ lo, int n4)
{
    int i = blockIdx.x * 256 + threadIdx.x;
    if (i >= n4) return;
    float4 a = ((const float4*)in)[i];
    __nv_bfloat16 h0 = __float2bfloat16(a.x), h1 = __float2bfloat16(a.y);
    __nv_bfloat16 h2 = __float2bfloat16(a.z), h3 = __float2bfloat16(a.w);
    ((__nv_bfloat162*)hi)[i * 2 + 0] = __halves2bfloat162(h0, h1);
    ((__nv_bfloat162*)hi)[i * 2 + 1] = __halves2bfloat162(h2, h3);
    ((__nv_bfloat162*)lo)[i * 2 + 0] = __halves2bfloat162(
        __float2bfloat16(a.x - __bfloat162float(h0)),
        __float2bfloat16(a.y - __bfloat162float(h1)));
    ((__nv_bfloat162*)lo)[i * 2 + 1] = __halves2bfloat162(
        __float2bfloat16(a.z - __bfloat162float(h2)),
        __float2bfloat16(a.w - __bfloat162float(h3)));
}

// ===========================================================================
// Weight transpose + split
// ===========================================================================
__global__ __launch_bounds__(256) void transpose_split(
    const float* __restrict__ s0, const float* __restrict__ s1,
    const float* __restrict__ s2, const float* __restrict__ s3,
    __nv_bfloat16* __restrict__ bh, __nv_bfloat16* __restrict__ bl)
{
    __shared__ float t[32][33];
    const float* S = blockIdx.z == 0 ? s0 : blockIdx.z == 1 ? s1
                   : blockIdx.z == 2 ? s2 : s3;
    __nv_bfloat16* H = bh + (size_t)blockIdx.z * DM * DM;
    __nv_bfloat16* L = bl + (size_t)blockIdx.z * DM * DM;
    const int x = blockIdx.x * 32, y = blockIdx.y * 32;
    const int tx = threadIdx.x & 31, ty = threadIdx.x >> 5;
#pragma unroll
    for (int i = 0; i < 32; i += 8)
        t[ty + i][tx] = S[(size_t)(y + ty + i) * DM + x + tx];
    __syncthreads();
#pragma unroll
    for (int i = 0; i < 32; i += 8) {
        float a = t[tx][ty + i];
        __nv_bfloat16 h = __float2bfloat16(a);
        size_t idx = (size_t)(x + ty + i) * DM + y + tx;
        H[idx] = h;
        L[idx] = __float2bfloat16(a - __bfloat162float(h));
    }
}

// ===========================================================================
// prep_kv (unchanged)
// ===========================================================================
__global__ __launch_bounds__(256) void prep_kv(
    const float* __restrict__ kh, const float* __restrict__ vh,
    const float* __restrict__ remb, const float* __restrict__ rwb,
    const float* __restrict__ rbias,
    __nv_bfloat16* __restrict__ cbh, __nv_bfloat16* __restrict__ cbl,
    __nv_bfloat16* __restrict__ vbh, __nv_bfloat16* __restrict__ vbl,
    float* __restrict__ tsg)
{
    const int gw = (blockIdx.x * 256 + threadIdx.x) >> 5;
    const int lane = threadIdx.x & 31;
    const int b = gw >> 14, n = (gw >> 10) & 15, j = gw & 1023;

    const size_t src = (size_t)(b * QL + j) * DM + n * DH + lane * 2;
    float2 k2 = *(const float2*)(kh + src);
    float2 v2 = *(const float2*)(vh + src);
    const bool has = (j + 1) < QL;
    float2 r2 = make_float2(0.f, 0.f);
    if (has) r2 = *(const float2*)(remb + ((size_t)(j + 1) * NHEAD + n) * DH + lane * 2);
    float2 rw2 = *(const float2*)(rwb + n * DH + lane * 2);

    float cx = k2.x + r2.x, cy = k2.y + r2.y;
    const size_t o = ((size_t)(b * NHEAD + n) * QL + j) * DH + lane * 2;

    __nv_bfloat162 ch2 = __floats2bfloat162_rn(cx, cy);
    *(__nv_bfloat162*)(cbh + o) = ch2;
    *(__nv_bfloat162*)(cbl + o) = __floats2bfloat162_rn(
        cx - __bfloat162float(ch2.x), cy - __bfloat162float(ch2.y));
    __nv_bfloat162 vh2 = __floats2bfloat162_rn(v2.x, v2.y);
    *(__nv_bfloat162*)(vbh + o) = vh2;
    *(__nv_bfloat162*)(vbl + o) = __floats2bfloat162_rn(
        v2.x - __bfloat162float(vh2.x), v2.y - __bfloat162float(vh2.y));

    float dot = rw2.x * k2.x + rw2.y * k2.y;
#pragma unroll
    for (int off = 16; off; off >>= 1)
        dot += __shfl_xor_sync(0xffffffffu, dot, off);
    if (lane == 0)
        tsg[(size_t)(b * NHEAD + n) * QL + j] =
            dot + (has ? rbias[(size_t)(j + 1) * NHEAD + n] : 0.f);
}

// ===========================================================================
// bf16x3 GEMM v2: CTA tile 128x128, warp tile 32x64 (8 warps 4x2).
// Multi-matrix: mat = blockIdx.x >> 3 selects weight matrix + output.
// mat==0 with qh_out!=null writes bf16 hi/lo split directly; else fp32.
// ===========================================================================
#define GK 1024
#define NCH 32
#define STG2 32768             // Ah 8K | Al 8K | Bh 8K | Bl 8K
#define SMEM_GEMM (3 * STG2)   // 98304

__global__ __launch_bounds__(256, 2) void gemm_bf16x3(
    const __nv_bfloat16* __restrict__ Ah, const __nv_bfloat16* __restrict__ Al,
    const __nv_bfloat16* __restrict__ Bh, const __nv_bfloat16* __restrict__ Bl,
    float* __restrict__ F0, float* __restrict__ F1, float* __restrict__ F2,
    __nv_bfloat16* __restrict__ Qh, __nv_bfloat16* __restrict__ Ql)
{
    extern __shared__ char smem[];
    const uint32_t sb = smem_to_u32(smem);
    const int tid = threadIdx.x;
    const int wid = tid >> 5, lane = tid & 31;
    const int wm = wid >> 1, wn = wid & 1;      // 4 x 2 warps
    const int mat = blockIdx.x >> 3;
    const int c0 = (blockIdx.x & 7) * 128;
    const int r0 = blockIdx.y * 128;

    const char* AgH = (const char*)(Ah + (size_t)r0 * GK);
    const char* AgL = (const char*)(Al + (size_t)r0 * GK);
    const char* BgH = (const char*)(Bh + (size_t)mat * DM * DM + (size_t)c0 * GK);
    const char* BgL = (const char*)(Bl + (size_t)mat * DM * DM + (size_t)c0 * GK);

    // per stage: 512 16B-chunks each of Ah/Al/Bh/Bl; 2 per thread each
    auto load_stage = [&](int st, int ck) {
        const uint32_t s0 = sb + st * STG2;
        const size_t gofs = (size_t)ck * 64;
#pragma unroll
        for (int h = 0; h < 2; ++h) {
            int idx = h * 256 + tid;
            int row = idx >> 2, ch = idx & 3;
            uint32_t o = SW64(row, ch);
            size_t g = (size_t)row * 2048 + gofs + ch * 16;
            CP_ASYNC16(s0 + o, AgH + g);
            CP_ASYNC16(s0 + 8192 + o, AgL + g);
            CP_ASYNC16(s0 + 16384 + o, BgH + g);
            CP_ASYNC16(s0 + 24576 + o, BgL + g);
        }
    };

    load_stage(0, 0); CP_ASYNC_COMMIT();
    load_stage(1, 1); CP_ASYNC_COMMIT();

    float acc[2][8][4];
#pragma unroll
    for (int mt = 0; mt < 2; ++mt)
#pragma unroll
        for (int nt = 0; nt < 8; ++nt)
#pragma unroll
            for (int r = 0; r < 4; ++r) acc[mt][nt][r] = 0.f;

    const int sub = lane >> 3, l7 = lane & 7;

    for (int i = 0; i < NCH; ++i) {
        if (i + 2 < NCH) load_stage((i + 2) % 3, i + 2);
        CP_ASYNC_COMMIT();
        CP_ASYNC_WAIT2();
        __syncthreads();

        const uint32_t sA = sb + (i % 3) * STG2;
        const uint32_t sB = sA + 16384;

#pragma unroll
        for (int ks = 0; ks < 2; ++ks) {
            uint32_t ah[2][4], al[2][4];
#pragma unroll
            for (int mt = 0; mt < 2; ++mt) {
                int row = wm * 32 + mt * 16 + ((sub & 1) << 3) + l7;
                int ch = 2 * ks + (sub >> 1);
                uint32_t off = SW64(row, ch);
                LDSM4(ah[mt][0], ah[mt][1], ah[mt][2], ah[mt][3], sA + off);
                LDSM4(al[mt][0], al[mt][1], al[mt][2], al[mt][3], sA + 8192 + off);
            }
#pragma unroll
            for (int ntp = 0; ntp < 4; ++ntp) {
                int row = wn * 64 + ntp * 16 + ((sub >> 1) << 3) + l7;
                int ch = 2 * ks + (sub & 1);
                uint32_t off = SW64(row, ch);
                uint32_t bh2[2][2], bl2[2][2];
                LDSM4(bh2[0][0], bh2[0][1], bh2[1][0], bh2[1][1], sB + off);
                LDSM4(bl2[0][0], bl2[0][1], bl2[1][0], bl2[1][1], sB + 8192 + off);
#pragma unroll
                for (int h = 0; h < 2; ++h) {
                    const int nt = 2 * ntp + h;
#pragma unroll
                    for (int mt = 0; mt < 2; ++mt) {
                        MMA_BF16(acc[mt][nt], ah[mt], bh2[h]);
                        MMA_BF16(acc[mt][nt], ah[mt], bl2[h]);
                        MMA_BF16(acc[mt][nt], al[mt], bh2[h]);
                    }
                }
            }
        }
        __syncthreads();
    }

    // epilogue
    const bool qsplit = (Qh != nullptr) && (mat == 0);
    float* F = (mat == 0) ? F0 : (mat == 1) ? F1 : F2;
#pragma unroll
    for (int mt = 0; mt < 2; ++mt)
#pragma unroll
        for (int nt = 0; nt < 8; ++nt) {
            int row = r0 + wm * 32 + mt * 16 + (lane >> 2);
            int col = c0 + wn * 64 + nt * 8 + 2 * (lane & 3);
            size_t p0 = (size_t)row * DM + col;
            size_t p1 = (size_t)(row + 8) * DM + col;
            if (qsplit) {
                float v0 = acc[mt][nt][0], v1 = acc[mt][nt][1];
                float v2 = acc[mt][nt][2], v3 = acc[mt][nt][3];
                __nv_bfloat162 h01 = __floats2bfloat162_rn(v0, v1);
                __nv_bfloat162 h23 = __floats2bfloat162_rn(v2, v3);
                *(__nv_bfloat162*)(Qh + p0) = h01;
                *(__nv_bfloat162*)(Qh + p1) = h23;
                *(__nv_bfloat162*)(Ql + p0) = __floats2bfloat162_rn(
                    v0 - __bfloat162float(h01.x), v1 - __bfloat162float(h01.y));
                *(__nv_bfloat162*)(Ql + p1) = __floats2bfloat162_rn(
                    v2 - __bfloat162float(h23.x), v3 - __bfloat162float(h23.y));
            } else {
                *(float2*)(F + p0) = make_float2(acc[mt][nt][0], acc[mt][nt][1]);
                *(float2*)(F + p1) = make_float2(acc[mt][nt][2], acc[mt][nt][3]);
            }
        }
}

// ===========================================================================
// MMA flash attention (unchanged from R4)
// ===========================================================================
#define ATT_STG 33024
#define ATT_SMEM (16384 + 2 * ATT_STG)

__global__ __launch_bounds__(128) void attn_mma(
    const __nv_bfloat16* __restrict__ qbh, const __nv_bfloat16* __restrict__ qbl,
    const __nv_bfloat16* __restrict__ cbh, const __nv_bfloat16* __restrict__ cbl,
    const __nv_bfloat16* __restrict__ vbh, const __nv_bfloat16* __restrict__ vbl,
    const float* __restrict__ tsg,
    __nv_bfloat16* __restrict__ avh, __nv_bfloat16* __restrict__ avl)
{
    extern __shared__ char sm[];
    const uint32_t sb = smem_to_u32(sm);
    const uint32_t sQh = sb, sQl = sb + 8192;

    const int tid = threadIdx.x;
    const int wid = tid >> 5, lane = tid & 31;
    const int sub = lane >> 3, l7 = lane & 7;
    const int i0 = blockIdx.x * 64, n = blockIdx.y, b = blockIdx.z;

    const char* qhg = (const char*)qbh + ((size_t)(b * QL + i0) * DM + n * DH) * 2;
    const char* qlg = (const char*)qbl + ((size_t)(b * QL + i0) * DM + n * DH) * 2;
#pragma unroll
    for (int r = 0; r < 4; ++r) {
        int id = r * 128 + tid;
        int row = id >> 3, ch = id & 7;
        uint32_t o = SWOFF(row, ch);
        CP_ASYNC16(sQh + o, qhg + (size_t)row * 2048 + ch * 16);
        CP_ASYNC16(sQl + o, qlg + (size_t)row * 2048 + ch * 16);
    }
    CP_ASYNC_COMMIT();

    const size_t kvb = ((size_t)(b * NHEAD + n) * QL) * DH * 2;
    const char* chg = (const char*)cbh + kvb;
    const char* clg = (const char*)cbl + kvb;
    const char* vhg = (const char*)vbh + kvb;
    const char* vlg = (const char*)vbl + kvb;
    const char* tg = (const char*)(tsg + (size_t)(b * NHEAD + n) * QL);

    auto load_stage = [&](int s, int jt) {
        const uint32_t st = sb + 16384 + s * ATT_STG;
        const size_t go = (size_t)jt * 64 * 128;
#pragma unroll
        for (int r = 0; r < 4; ++r) {
            int id = r * 128 + tid;
            int row = id >> 3, ch = id & 7;
            uint32_t o = SWOFF(row, ch);
            size_t g = go + (size_t)row * 128 + ch * 16;
            CP_ASYNC16(st + o, chg + g);
            CP_ASYNC16(st + 8192 + o, clg + g);
            CP_ASYNC16(st + 16384 + o, vhg + g);
            CP_ASYNC16(st + 24576 + o, vlg + g);
        }
        if (tid < 16) CP_ASYNC16(st + 32768 + tid * 16, tg + (size_t)jt * 256 + tid * 16);
    };

    load_stage(0, 0); CP_ASYNC_COMMIT();
    load_stage(1, 1); CP_ASYNC_COMMIT();

    uint32_t qhf[4][4], qlf[4][4];
    float o_[8][4];
    float m0 = -1e30f, m1 = -1e30f, l0 = 0.f, l1 = 0.f;
#pragma unroll
    for (int t = 0; t < 8; ++t)
#pragma unroll
        for (int r = 0; r < 4; ++r) o_[t][r] = 0.f;

    for (int jt = 0; jt < 16; ++jt) {
        CP_ASYNC_WAIT1();
        __syncthreads();

        if (jt == 0) {
#pragma unroll
            for (int kc = 0; kc < 4; ++kc) {
                int row = wid * 16 + ((sub & 1) << 3) + l7;
                int ch = 2 * kc + (sub >> 1);
                uint32_t o = SWOFF(row, ch);
                LDSM4(qhf[kc][0], qhf[kc][1], qhf[kc][2], qhf[kc][3], sQh + o);
                LDSM4(qlf[kc][0], qlf[kc][1], qlf[kc][2], qlf[kc][3], sQl + o);
            }
        }

        const uint32_t st = sb + 16384 + (jt & 1) * ATT_STG;
        const float* tsp = (const float*)(sm + 16384 + (jt & 1) * ATT_STG + 32768);

        float s[8][4];
#pragma unroll
        for (int t = 0; t < 8; ++t)
#pragma unroll
            for (int r = 0; r < 4; ++r) s[t][r] = 0.f;

#pragma unroll
        for (int kc = 0; kc < 4; ++kc) {
#pragma unroll
            for (int p = 0; p < 4; ++p) {
                int row = p * 16 + ((sub >> 1) << 3) + l7;
                int ch = 2 * kc + (sub & 1);
                uint32_t o = SWOFF(row, ch);
                uint32_t bh[2][2], bl[2][2];
                LDSM4(bh[0][0], bh[0][1], bh[1][0], bh[1][1], st + o);
                LDSM4(bl[0][0], bl[0][1], bl[1][0], bl[1][1], st + 8192 + o);
#pragma unroll
                for (int h = 0; h < 2; ++h) {
                    MMA_BF16(s[2 * p + h], qhf[kc], bh[h]);
                    MMA_BF16(s[2 * p + h], qhf[kc], bl[h]);
                    MMA_BF16(s[2 * p + h], qlf[kc], bh[h]);
                }
            }
        }

#pragma unroll
        for (int t = 0; t < 8; ++t) {
            float2 tv = *(const float2*)(tsp + t * 8 + (lane & 3) * 2);
            s[t][0] = (s[t][0] + tv.x) * 0.125f;
            s[t][1] = (s[t][1] + tv.y) * 0.125f;
            s[t][2] = (s[t][2] + tv.x) * 0.125f;
            s[t][3] = (s[t][3] + tv.y) * 0.125f;
        }

        float mx0 = -1e30f, mx1 = -1e30f;
#pragma unroll
        for (int t = 0; t < 8; ++t) {
            mx0 = fmaxf(mx0, fmaxf(s[t][0], s[t][1]));
            mx1 = fmaxf(mx1, fmaxf(s[t][2], s[t][3]));
        }
        mx0 = fmaxf(mx0, __shfl_xor_sync(0xffffffffu, mx0, 1));
        mx0 = fmaxf(mx0, __shfl_xor_sync(0xffffffffu, mx0, 2));
        mx1 = fmaxf(mx1, __shfl_xor_sync(0xffffffffu, mx1, 1));
        mx1 = fmaxf(mx1, __shfl_xor_sync(0xffffffffu, mx1, 2));
        const float nm0 = fmaxf(m0, mx0), nm1 = fmaxf(m1, mx1);
        const float a0 = __expf(m0 - nm0), a1 = __expf(m1 - nm1);
        m0 = nm0; m1 = nm1;

        float sum0 = 0.f, sum1 = 0.f;
#pragma unroll
        for (int t = 0; t < 8; ++t) {
            s[t][0] = __expf(s[t][0] - nm0);
            s[t][1] = __expf(s[t][1] - nm0);
            s[t][2] = __expf(s[t][2] - nm1);
            s[t][3] = __expf(s[t][3] - nm1);
            sum0 += s[t][0] + s[t][1];
            sum1 += s[t][2] + s[t][3];
        }
        sum0 += __shfl_xor_sync(0xffffffffu, sum0, 1);
        sum0 += __shfl_xor_sync(0xffffffffu, sum0, 2);
        sum1 += __shfl_xor_sync(0xffffffffu, sum1, 1);
        sum1 += __shfl_xor_sync(0xffffffffu, sum1, 2);
        l0 = l0 * a0 + sum0;
        l1 = l1 * a1 + sum1;
#pragma unroll
        for (int t = 0; t < 8; ++t) {
            o_[t][0] *= a0; o_[t][1] *= a0;
            o_[t][2] *= a1; o_[t][3] *= a1;
        }

#pragma unroll
        for (int kc = 0; kc < 4; ++kc) {
            uint32_t ah[4], al[4];
#pragma unroll
            for (int h = 0; h < 2; ++h) {
                const int t = 2 * kc + h;
                __nv_bfloat162 p01 = __floats2bfloat162_rn(s[t][0], s[t][1]);
                __nv_bfloat162 p23 = __floats2bfloat162_rn(s[t][2], s[t][3]);
                ah[2 * h + 0] = *(uint32_t*)&p01;
                ah[2 * h + 1] = *(uint32_t*)&p23;
                __nv_bfloat162 q01 = __floats2bfloat162_rn(
                    s[t][0] - __bfloat162float(p01.x),
                    s[t][1] - __bfloat162float(p01.y));
                __nv_bfloat162 q23 = __floats2bfloat162_rn(
                    s[t][2] - __bfloat162float(p23.x),
                    s[t][3] - __bfloat162float(p23.y));
                al[2 * h + 0] = *(uint32_t*)&q01;
                al[2 * h + 1] = *(uint32_t*)&q23;
            }
#pragma unroll
            for (int g = 0; g < 4; ++g) {
                int row = 16 * kc + ((sub & 1) << 3) + l7;
                int ch = 2 * g + (sub >> 1);
                uint32_t o = SWOFF(row, ch);
                uint32_t vh[2][2], vl[2][2];
                LDSM4T(vh[0][0], vh[0][1], vh[1][0], vh[1][1], st + 16384 + o);
                LDSM4T(vl[0][0], vl[0][1], vl[1][0], vl[1][1], st + 24576 + o);
#pragma unroll
                for (int h = 0; h < 2; ++h) {
                    MMA_BF16(o_[2 * g + h], ah, vh[h]);
                    MMA_BF16(o_[2 * g + h], ah, vl[h]);
                    MMA_BF16(o_[2 * g + h], al, vh[h]);
                }
            }
        }

        __syncthreads();
        if (jt + 2 < 16) load_stage(jt & 1, jt + 2);
        CP_ASYNC_COMMIT();
    }

    const float inv0 = 1.f / l0, inv1 = 1.f / l1;
    const int row0 = i0 + wid * 16 + (lane >> 2);
#pragma unroll
    for (int t = 0; t < 8; ++t) {
        const int col = n * DH + t * 8 + (lane & 3) * 2;
        float v0 = o_[t][0] * inv0, v1 = o_[t][1] * inv0;
        float v2 = o_[t][2] * inv1, v3 = o_[t][3] * inv1;
        __nv_bfloat162 h01 = __floats2bfloat162_rn(v0, v1);
        __nv_bfloat162 h23 = __floats2bfloat162_rn(v2, v3);
        size_t p0 = (size_t)(b * QL + row0) * DM + col;
        size_t p1 = (size_t)(b * QL + row0 + 8) * DM + col;
        *(__nv_bfloat162*)(avh + p0) = h01;
        *(__nv_bfloat162*)(avh + p1) = h23;
        *(__nv_bfloat162*)(avl + p0) = __floats2bfloat162_rn(
            v0 - __bfloat162float(h01.x), v1 - __bfloat162float(h01.y));
        *(__nv_bfloat162*)(avl + p1) = __floats2bfloat162_rn(
            v2 - __bfloat162float(h23.x), v3 - __bfloat162float(h23.y));
    }
}

// ===========================================================================
// Residual + LayerNorm (unchanged)
// ===========================================================================
__global__ __launch_bounds__(256) void ln_kernel(
    const float* __restrict__ w, const float* __restrict__ ao,
    const float* __restrict__ gamma, const float* __restrict__ beta,
    float* __restrict__ out)
{
    __shared__ float ssum[8], ssq[8];
    const int row = blockIdx.x;
    const int tid = threadIdx.x;
    const size_t base = (size_t)row * DM + tid * 4;

    float4 x = *(const float4*)(w + base);
    float4 a = *(const float4*)(ao + base);
    x.x += a.x; x.y += a.y; x.z += a.z; x.w += a.w;

    float sum = x.x + x.y + x.z + x.w;
    float sq = x.x * x.x + x.y * x.y + x.z * x.z + x.w * x.w;
#pragma unroll
    for (int off = 16; off; off >>= 1) {
        sum += __shfl_xor_sync(0xffffffffu, sum, off);
        sq += __shfl_xor_sync(0xffffffffu, sq, off);
    }
    const int wid = tid >> 5;
    if ((tid & 31) == 0) { ssum[wid] = sum; ssq[wid] = sq; }
    __syncthreads();
    sum = 0.f; sq = 0.f;
#pragma unroll
    for (int i = 0; i < 8; ++i) { sum += ssum[i]; sq += ssq[i]; }

    const float mu = sum * (1.f / DM);
    const float var = sq * (1.f / DM) - mu * mu;
    const float inv = rsqrtf(var + 1e-5f);

    float4 g = *(const float4*)(gamma + (size_t)tid * 4);
    float4 be = *(const float4*)(beta + (size_t)tid * 4);
    float4 r;
    r.x = (x.x - mu) * inv * g.x + be.x;
    r.y = (x.y - mu) * inv * g.y + be.y;
    r.z = (x.z - mu) * inv * g.z + be.z;
    r.w = (x.w - mu) * inv * g.w + be.w;
    *(float4*)(out + base) = r;
}

// ===========================================================================
extern "C" void kernel_launch(void* const* d_in, const int* in_sizes, int n_in,
                              void* d_out, int out_size)
{
    (void)in_sizes; (void)n_in; (void)out_size;
    const float* w      = (const float*)d_in[0];
    const float* r_emb  = (const float*)d_in[1];
    const float* r_w_b  = (const float*)d_in[2];
    const float* r_bias = (const float*)d_in[3];
    const float* Wq     = (const float*)d_in[4];
    const float* Wk     = (const float*)d_in[5];
    const float* Wv     = (const float*)d_in[6];
    const float* Wo     = (const float*)d_in[7];
    const float* gamma  = (const float*)d_in[8];
    const float* beta   = (const float*)d_in[9];
    float* out = (float*)d_out;

    float *kh, *vh, *ao, *tsg;
    __nv_bfloat16 *wh, *wl, *avh, *avl, *bh, *bl;
    __nv_bfloat16 *qbh, *qbl, *cbh, *cbl, *vbh, *vbl;
    cudaGetSymbolAddress((void**)&kh, g_kh);
    cudaGetSymbolAddress((void**)&vh, g_vh);
    cudaGetSymbolAddress((void**)&ao, g_ao);
    cudaGetSymbolAddress((void**)&wh, g_wh);
    cudaGetSymbolAddress((void**)&wl, g_wl);
    cudaGetSymbolAddress((void**)&avh, g_avh);
    cudaGetSymbolAddress((void**)&avl, g_avl);
    cudaGetSymbolAddress((void**)&bh, g_bh);
    cudaGetSymbolAddress((void**)&bl, g_bl);
    cudaGetSymbolAddress((void**)&qbh, g_qbh);
    cudaGetSymbolAddress((void**)&qbl, g_qbl);
    cudaGetSymbolAddress((void**)&cbh, g_cbh);
    cudaGetSymbolAddress((void**)&cbl, g_cbl);
    cudaGetSymbolAddress((void**)&vbh, g_vbh);
    cudaGetSymbolAddress((void**)&vbl, g_vbl);
    cudaGetSymbolAddress((void**)&tsg, g_ts);

    const int n4 = MTOT * DM / 4;
    split_act<<<(n4 + 255) / 256, 256>>>(w, wh, wl, n4);
    transpose_split<<<dim3(32, 32, 4), 256>>>(Wq, Wk, Wv, Wo, bh, bl);

    cudaFuncSetAttribute(gemm_bf16x3,
                         cudaFuncAttributeMaxDynamicSharedMemorySize, SMEM_GEMM);
    // fused QKV: grid.x = 24 (3 matrices x 8 col tiles)
    gemm_bf16x3<<<dim3(24, 32), 256, SMEM_GEMM>>>(
        wh, wl, bh, bl, nullptr, kh, vh, qbh, qbl);

    prep_kv<<<(BB * NHEAD * QL) / 8, 256>>>(kh, vh, r_emb, r_w_b, r_bias,
                                            cbh, cbl, vbh, vbl, tsg);

    cudaFuncSetAttribute(attn_mma,
                         cudaFuncAttributeMaxDynamicSharedMemorySize, ATT_SMEM);
    attn_mma<<<dim3(QL / 64, NHEAD, BB), 128, ATT_SMEM>>>(
        qbh, qbl, cbh, cbl, vbh, vbl, tsg, avh, avl);

    // output projection: Wo is matrix index 3 in bh/bl; point base at it
    gemm_bf16x3<<<dim3(8, 32), 256, SMEM_GEMM>>>(
        avh, avl, bh + 3 * (size_t)DM * DM, bl + 3 * (size_t)DM * DM,
        ao, nullptr, nullptr, nullptr, nullptr);

    ln_kernel<<<MTOT, 256>>>(w, ao, gamma, beta, out);
}

// round 6
// speedup vs baseline: 3.1543x; 1.0657x over previous
#include <cuda_runtime.h>
#include <cuda_bf16.h>
#include <cstdint>

#define BB 4
#define QL 1024
#define DM 1024
#define NHEAD 16
#define DH 64
#define MTOT (BB * QL)  // 4096

// fp32 scratch
__device__ float g_ao[(size_t)MTOT * DM];
// bf16 split operands
__device__ __nv_bfloat16 g_wh[(size_t)MTOT * DM];
__device__ __nv_bfloat16 g_wl[(size_t)MTOT * DM];
__device__ __nv_bfloat16 g_avh[(size_t)MTOT * DM];
__device__ __nv_bfloat16 g_avl[(size_t)MTOT * DM];
__device__ __nv_bfloat16 g_bh[(size_t)4 * DM * DM];
__device__ __nv_bfloat16 g_bl[(size_t)4 * DM * DM];
// attention operands
__device__ __nv_bfloat16 g_qbh[(size_t)MTOT * DM];
__device__ __nv_bfloat16 g_qbl[(size_t)MTOT * DM];
__device__ __nv_bfloat16 g_cbh[(size_t)BB * NHEAD * QL * DH];
__device__ __nv_bfloat16 g_cbl[(size_t)BB * NHEAD * QL * DH];
__device__ __nv_bfloat16 g_vbh[(size_t)BB * NHEAD * QL * DH];
__device__ __nv_bfloat16 g_vbl[(size_t)BB * NHEAD * QL * DH];
__device__ float g_ts[(size_t)BB * NHEAD * QL];

// ===========================================================================
// PTX helpers (portable sm_80/90-class only)
// ===========================================================================
__device__ __forceinline__ uint32_t smem_to_u32(const void* p) {
    uint32_t a;
    asm("{ .reg .u64 t; cvta.to.shared.u64 t, %1; cvt.u32.u64 %0, t; }"
        : "=r"(a) : "l"(p));
    return a;
}
#define CP_ASYNC16(s, g) \
    asm volatile("cp.async.cg.shared.global [%0], [%1], 16;" :: "r"(s), "l"(g) : "memory")
#define CP_ASYNC_COMMIT() asm volatile("cp.async.commit_group;" ::: "memory")
#define CP_ASYNC_WAIT1() asm volatile("cp.async.wait_group 1;" ::: "memory")

#define LDSM4(r0, r1, r2, r3, addr)                                            \
    asm volatile("ldmatrix.sync.aligned.m8n8.x4.shared.b16 {%0,%1,%2,%3}, [%4];" \
                 : "=r"(r0), "=r"(r1), "=r"(r2), "=r"(r3) : "r"(addr))
#define LDSM4T(r0, r1, r2, r3, addr)                                           \
    asm volatile("ldmatrix.sync.aligned.m8n8.x4.trans.shared.b16 {%0,%1,%2,%3}, [%4];" \
                 : "=r"(r0), "=r"(r1), "=r"(r2), "=r"(r3) : "r"(addr))

#define MMA_BF16(d, a, b)                                                      \
    asm volatile("mma.sync.aligned.m16n8k16.row.col.f32.bf16.bf16.f32 "        \
                 "{%0,%1,%2,%3}, {%4,%5,%6,%7}, {%8,%9}, {%0,%1,%2,%3};"       \
                 : "+f"((d)[0]), "+f"((d)[1]), "+f"((d)[2]), "+f"((d)[3])      \
                 : "r"((a)[0]), "r"((a)[1]), "r"((a)[2]), "r"((a)[3]),         \
                   "r"((b)[0]), "r"((b)[1]))

// 64B rows (32 bf16), 4x16B chunks
#define SW64(row, ch) ((row) * 64 + (((ch) ^ (((row) >> 1) & 3)) << 4))
// 128B rows (64 bf16), 8x16B chunks
#define SWOFF(row, ch) ((row) * 128 + (((ch) ^ ((row) & 7)) << 4))

// ===========================================================================
// prep_all: z<4 -> weight transpose+split; z>=4 -> activation split
// ===========================================================================
__global__ __launch_bounds__(256) void prep_all(
    const float* __restrict__ w,
    const float* __restrict__ s0, const float* __restrict__ s1,
    const float* __restrict__ s2, const float* __restrict__ s3,
    __nv_bfloat16* __restrict__ wh, __nv_bfloat16* __restrict__ wl,
    __nv_bfloat16* __restrict__ bh, __nv_bfloat16* __restrict__ bl)
{
    const int z = blockIdx.z;
    if (z >= 4) {
        // split_act for w: 4096 blocks x 256 threads x float4
        int i = (((z - 4) * 32 + blockIdx.y) * 32 + blockIdx.x) * 256 + threadIdx.x;
        float4 a = ((const float4*)w)[i];
        __nv_bfloat16 h0 = __float2bfloat16(a.x), h1 = __float2bfloat16(a.y);
        __nv_bfloat16 h2 = __float2bfloat16(a.z), h3 = __float2bfloat16(a.w);
        ((__nv_bfloat162*)wh)[i * 2 + 0] = __halves2bfloat162(h0, h1);
        ((__nv_bfloat162*)wh)[i * 2 + 1] = __halves2bfloat162(h2, h3);
        ((__nv_bfloat162*)wl)[i * 2 + 0] = __halves2bfloat162(
            __float2bfloat16(a.x - __bfloat162float(h0)),
            __float2bfloat16(a.y - __bfloat162float(h1)));
        ((__nv_bfloat162*)wl)[i * 2 + 1] = __halves2bfloat162(
            __float2bfloat16(a.z - __bfloat162float(h2)),
            __float2bfloat16(a.w - __bfloat162float(h3)));
        return;
    }
    __shared__ float t[32][33];
    const float* S = z == 0 ? s0 : z == 1 ? s1 : z == 2 ? s2 : s3;
    __nv_bfloat16* H = bh + (size_t)z * DM * DM;
    __nv_bfloat16* L = bl + (size_t)z * DM * DM;
    const int x = blockIdx.x * 32, y = blockIdx.y * 32;
    const int tx = threadIdx.x & 31, ty = threadIdx.x >> 5;
#pragma unroll
    for (int i = 0; i < 32; i += 8)
        t[ty + i][tx] = S[(size_t)(y + ty + i) * DM + x + tx];
    __syncthreads();
#pragma unroll
    for (int i = 0; i < 32; i += 8) {
        float a = t[tx][ty + i];
        __nv_bfloat16 h = __float2bfloat16(a);
        size_t idx = (size_t)(x + ty + i) * DM + y + tx;
        H[idx] = h;
        L[idx] = __float2bfloat16(a - __bfloat162float(h));
    }
}

// ===========================================================================
// bf16x3 GEMM: CTA 128x128, warp 32x64, BK=32, 3-stage, single barrier/chunk.
// is_qkv: mat 0 -> Q bf16 split out; mat 1 -> C=K+r_emb split + ts;
//         mat 2 -> V split. Else fp32 to F0.
// ===========================================================================
#define GK 1024
#define NCH 32
#define STG2 32768
#define SMEM_GEMM (3 * STG2)

__global__ __launch_bounds__(256, 2) void gemm_bf16x3(
    const __nv_bfloat16* __restrict__ Ah, const __nv_bfloat16* __restrict__ Al,
    const __nv_bfloat16* __restrict__ Bh, const __nv_bfloat16* __restrict__ Bl,
    float* __restrict__ F0,
    const float* __restrict__ remb, const float* __restrict__ rwb,
    const float* __restrict__ rbias,
    __nv_bfloat16* __restrict__ Qh, __nv_bfloat16* __restrict__ Ql,
    __nv_bfloat16* __restrict__ Cbh, __nv_bfloat16* __restrict__ Cbl,
    __nv_bfloat16* __restrict__ Vbh, __nv_bfloat16* __restrict__ Vbl,
    float* __restrict__ tsg, int is_qkv)
{
    extern __shared__ char smem[];
    const uint32_t sb = smem_to_u32(smem);
    const int tid = threadIdx.x;
    const int wid = tid >> 5, lane = tid & 31;
    const int wm = wid >> 1, wn = wid & 1;
    const int mat = blockIdx.x >> 3;
    const int c0 = (blockIdx.x & 7) * 128;
    const int r0 = blockIdx.y * 128;

    const char* AgH = (const char*)(Ah + (size_t)r0 * GK);
    const char* AgL = (const char*)(Al + (size_t)r0 * GK);
    const char* BgH = (const char*)(Bh + (size_t)mat * DM * DM + (size_t)c0 * GK);
    const char* BgL = (const char*)(Bl + (size_t)mat * DM * DM + (size_t)c0 * GK);

    auto load_stage = [&](int st, int ck) {
        const uint32_t s0 = sb + st * STG2;
        const size_t gofs = (size_t)ck * 64;
#pragma unroll
        for (int h = 0; h < 2; ++h) {
            int idx = h * 256 + tid;
            int row = idx >> 2, ch = idx & 3;
            uint32_t o = SW64(row, ch);
            size_t g = (size_t)row * 2048 + gofs + ch * 16;
            CP_ASYNC16(s0 + o, AgH + g);
            CP_ASYNC16(s0 + 8192 + o, AgL + g);
            CP_ASYNC16(s0 + 16384 + o, BgH + g);
            CP_ASYNC16(s0 + 24576 + o, BgL + g);
        }
    };

    load_stage(0, 0); CP_ASYNC_COMMIT();
    load_stage(1, 1); CP_ASYNC_COMMIT();

    float acc[2][8][4];
#pragma unroll
    for (int mt = 0; mt < 2; ++mt)
#pragma unroll
        for (int nt = 0; nt < 8; ++nt)
#pragma unroll
            for (int r = 0; r < 4; ++r) acc[mt][nt][r] = 0.f;

    const int sub = lane >> 3, l7 = lane & 7;

    for (int i = 0; i < NCH; ++i) {
        CP_ASYNC_WAIT1();
        __syncthreads();
        if (i + 2 < NCH) load_stage((i + 2) % 3, i + 2);
        CP_ASYNC_COMMIT();

        const uint32_t sA = sb + (i % 3) * STG2;
        const uint32_t sB = sA + 16384;

#pragma unroll
        for (int ks = 0; ks < 2; ++ks) {
            uint32_t ah[2][4], al[2][4];
#pragma unroll
            for (int mt = 0; mt < 2; ++mt) {
                int row = wm * 32 + mt * 16 + ((sub & 1) << 3) + l7;
                int ch = 2 * ks + (sub >> 1);
                uint32_t off = SW64(row, ch);
                LDSM4(ah[mt][0], ah[mt][1], ah[mt][2], ah[mt][3], sA + off);
                LDSM4(al[mt][0], al[mt][1], al[mt][2], al[mt][3], sA + 8192 + off);
            }
#pragma unroll
            for (int ntp = 0; ntp < 4; ++ntp) {
                int row = wn * 64 + ntp * 16 + ((sub >> 1) << 3) + l7;
                int ch = 2 * ks + (sub & 1);
                uint32_t off = SW64(row, ch);
                uint32_t bh2[2][2], bl2[2][2];
                LDSM4(bh2[0][0], bh2[0][1], bh2[1][0], bh2[1][1], sB + off);
                LDSM4(bl2[0][0], bl2[0][1], bl2[1][0], bl2[1][1], sB + 8192 + off);
#pragma unroll
                for (int h = 0; h < 2; ++h) {
                    const int nt = 2 * ntp + h;
#pragma unroll
                    for (int mt = 0; mt < 2; ++mt) {
                        MMA_BF16(acc[mt][nt], ah[mt], bh2[h]);
                        MMA_BF16(acc[mt][nt], ah[mt], bl2[h]);
                        MMA_BF16(acc[mt][nt], al[mt], bh2[h]);
                    }
                }
            }
        }
    }

    // ------------------------- epilogue -------------------------
    if (is_qkv && mat == 0) {
        // Q: bf16 hi/lo split, layout [row, col]
#pragma unroll
        for (int mt = 0; mt < 2; ++mt)
#pragma unroll
            for (int nt = 0; nt < 8; ++nt) {
                int row = r0 + wm * 32 + mt * 16 + (lane >> 2);
                int col = c0 + wn * 64 + nt * 8 + 2 * (lane & 3);
                size_t p0 = (size_t)row * DM + col;
                size_t p1 = (size_t)(row + 8) * DM + col;
                float v0 = acc[mt][nt][0], v1 = acc[mt][nt][1];
                float v2 = acc[mt][nt][2], v3 = acc[mt][nt][3];
                __nv_bfloat162 h01 = __floats2bfloat162_rn(v0, v1);
                __nv_bfloat162 h23 = __floats2bfloat162_rn(v2, v3);
                *(__nv_bfloat162*)(Qh + p0) = h01;
                *(__nv_bfloat162*)(Qh + p1) = h23;
                *(__nv_bfloat162*)(Ql + p0) = __floats2bfloat162_rn(
                    v0 - __bfloat162float(h01.x), v1 - __bfloat162float(h01.y));
                *(__nv_bfloat162*)(Ql + p1) = __floats2bfloat162_rn(
                    v2 - __bfloat162float(h23.x), v3 - __bfloat162float(h23.y));
            }
    } else if (is_qkv) {
        // K (mat==1): C = K + r_emb[j+1] split + ts; V (mat==2): V split.
        __nv_bfloat16* Oh = (mat == 1) ? Cbh : Vbh;
        __nv_bfloat16* Ol = (mat == 1) ? Cbl : Vbl;
        const int n = ((blockIdx.x & 7) << 1) + wn;   // global head
        float rwv[8][2];
        if (mat == 1) {
#pragma unroll
            for (int nt = 0; nt < 8; ++nt) {
                float2 t = *(const float2*)(rwb + n * DH + nt * 8 + 2 * (lane & 3));
                rwv[nt][0] = t.x; rwv[nt][1] = t.y;
            }
        }
#pragma unroll
        for (int mt = 0; mt < 2; ++mt) {
#pragma unroll
            for (int half = 0; half < 2; ++half) {
                const int row = r0 + wm * 32 + mt * 16 + (lane >> 2) + half * 8;
                const int b = row >> 10, j = row & 1023;
                const bool has = (j + 1) < QL;
                float dot = 0.f;
                float vals[8][2];
#pragma unroll
                for (int nt = 0; nt < 8; ++nt) {
                    float v0 = acc[mt][nt][half * 2 + 0];
                    float v1 = acc[mt][nt][half * 2 + 1];
                    if (mat == 1) {
                        dot += rwv[nt][0] * v0 + rwv[nt][1] * v1;
                        const int d = nt * 8 + 2 * (lane & 3);
                        float2 re = has
                            ? *(const float2*)(remb + ((size_t)(j + 1) * NHEAD + n) * DH + d)
                            : make_float2(0.f, 0.f);
                        v0 += re.x; v1 += re.y;
                    }
                    vals[nt][0] = v0; vals[nt][1] = v1;
                }
                const size_t base =
                    ((size_t)(b * NHEAD + n) * QL + j) * DH + 2 * (lane & 3);
#pragma unroll
                for (int nt = 0; nt < 8; ++nt) {
                    __nv_bfloat162 h2 = __floats2bfloat162_rn(vals[nt][0], vals[nt][1]);
                    *(__nv_bfloat162*)(Oh + base + nt * 8) = h2;
                    *(__nv_bfloat162*)(Ol + base + nt * 8) = __floats2bfloat162_rn(
                        vals[nt][0] - __bfloat162float(h2.x),
                        vals[nt][1] - __bfloat162float(h2.y));
                }
                if (mat == 1) {
                    dot += __shfl_xor_sync(0xffffffffu, dot, 1);
                    dot += __shfl_xor_sync(0xffffffffu, dot, 2);
                    if ((lane & 3) == 0)
                        tsg[(size_t)(b * NHEAD + n) * QL + j] =
                            dot + (has ? rbias[(size_t)(j + 1) * NHEAD + n] : 0.f);
                }
            }
        }
    } else {
        // Wo: fp32 out
#pragma unroll
        for (int mt = 0; mt < 2; ++mt)
#pragma unroll
            for (int nt = 0; nt < 8; ++nt) {
                int row = r0 + wm * 32 + mt * 16 + (lane >> 2);
                int col = c0 + wn * 64 + nt * 8 + 2 * (lane & 3);
                *(float2*)(F0 + (size_t)row * DM + col) =
                    make_float2(acc[mt][nt][0], acc[mt][nt][1]);
                *(float2*)(F0 + (size_t)(row + 8) * DM + col) =
                    make_float2(acc[mt][nt][2], acc[mt][nt][3]);
            }
    }
}

// ===========================================================================
// MMA flash attention: 2-stage pipeline, Q staged through stage 0, 3 CTAs/SM.
// ===========================================================================
#define ATT_STG 33024
#define ATT_SMEM (2 * ATT_STG)

__global__ __launch_bounds__(128, 3) void attn_mma(
    const __nv_bfloat16* __restrict__ qbh, const __nv_bfloat16* __restrict__ qbl,
    const __nv_bfloat16* __restrict__ cbh, const __nv_bfloat16* __restrict__ cbl,
    const __nv_bfloat16* __restrict__ vbh, const __nv_bfloat16* __restrict__ vbl,
    const float* __restrict__ tsg,
    __nv_bfloat16* __restrict__ avh, __nv_bfloat16* __restrict__ avl)
{
    extern __shared__ char sm[];
    const uint32_t sb = smem_to_u32(sm);

    const int tid = threadIdx.x;
    const int wid = tid >> 5, lane = tid & 31;
    const int sub = lane >> 3, l7 = lane & 7;
    const int i0 = blockIdx.x * 64, n = blockIdx.y, b = blockIdx.z;

    const size_t kvb = ((size_t)(b * NHEAD + n) * QL) * DH * 2;
    const char* chg = (const char*)cbh + kvb;
    const char* clg = (const char*)cbl + kvb;
    const char* vhg = (const char*)vbh + kvb;
    const char* vlg = (const char*)vbl + kvb;
    const char* tg = (const char*)(tsg + (size_t)(b * NHEAD + n) * QL);

    // --- group #1: Q -> stage0 ch/cl slots
    {
        const char* qhg = (const char*)qbh + ((size_t)(b * QL + i0) * DM + n * DH) * 2;
        const char* qlg = (const char*)qbl + ((size_t)(b * QL + i0) * DM + n * DH) * 2;
#pragma unroll
        for (int r = 0; r < 4; ++r) {
            int id = r * 128 + tid;
            int row = id >> 3, ch = id & 7;
            uint32_t o = SWOFF(row, ch);
            CP_ASYNC16(sb + o, qhg + (size_t)row * 2048 + ch * 16);
            CP_ASYNC16(sb + 8192 + o, qlg + (size_t)row * 2048 + ch * 16);
        }
        CP_ASYNC_COMMIT();
    }

    auto load_stage = [&](int s, int jt) {
        const uint32_t st = sb + s * ATT_STG;
        const size_t go = (size_t)jt * 64 * 128;
#pragma unroll
        for (int r = 0; r < 4; ++r) {
            int id = r * 128 + tid;
            int row = id >> 3, ch = id & 7;
            uint32_t o = SWOFF(row, ch);
            size_t g = go + (size_t)row * 128 + ch * 16;
            CP_ASYNC16(st + o, chg + g);
            CP_ASYNC16(st + 8192 + o, clg + g);
            CP_ASYNC16(st + 16384 + o, vhg + g);
            CP_ASYNC16(st + 24576 + o, vlg + g);
        }
        if (tid < 16) CP_ASYNC16(st + 32768 + tid * 16, tg + (size_t)jt * 256 + tid * 16);
    };

    load_stage(1, 0); CP_ASYNC_COMMIT();   // group #2: kv0 -> stage1

    CP_ASYNC_WAIT1();   // Q done (kv0 may pend)
    __syncthreads();

    uint32_t qhf[4][4], qlf[4][4];
#pragma unroll
    for (int kc = 0; kc < 4; ++kc) {
        int row = wid * 16 + ((sub & 1) << 3) + l7;
        int ch = 2 * kc + (sub >> 1);
        uint32_t o = SWOFF(row, ch);
        LDSM4(qhf[kc][0], qhf[kc][1], qhf[kc][2], qhf[kc][3], sb + o);
        LDSM4(qlf[kc][0], qlf[kc][1], qlf[kc][2], qlf[kc][3], sb + 8192 + o);
    }
    __syncthreads();   // all warps consumed Q; stage0 free

    load_stage(0, 1); CP_ASYNC_COMMIT();   // group #3: kv1 -> stage0

    float o_[8][4];
    float m0 = -1e30f, m1 = -1e30f, l0 = 0.f, l1 = 0.f;
#pragma unroll
    for (int t = 0; t < 8; ++t)
#pragma unroll
        for (int r = 0; r < 4; ++r) o_[t][r] = 0.f;

    for (int jt = 0; jt < 16; ++jt) {
        CP_ASYNC_WAIT1();
        __syncthreads();

        const int s = (jt + 1) & 1;
        const uint32_t st = sb + s * ATT_STG;
        const float* tsp = (const float*)(sm + s * ATT_STG + 32768);

        float sc[8][4];
#pragma unroll
        for (int t = 0; t < 8; ++t)
#pragma unroll
            for (int r = 0; r < 4; ++r) sc[t][r] = 0.f;

#pragma unroll
        for (int kc = 0; kc < 4; ++kc) {
#pragma unroll
            for (int p = 0; p < 4; ++p) {
                int row = p * 16 + ((sub >> 1) << 3) + l7;
                int ch = 2 * kc + (sub & 1);
                uint32_t o = SWOFF(row, ch);
                uint32_t bh[2][2], bl[2][2];
                LDSM4(bh[0][0], bh[0][1], bh[1][0], bh[1][1], st + o);
                LDSM4(bl[0][0], bl[0][1], bl[1][0], bl[1][1], st + 8192 + o);
#pragma unroll
                for (int h = 0; h < 2; ++h) {
                    MMA_BF16(sc[2 * p + h], qhf[kc], bh[h]);
                    MMA_BF16(sc[2 * p + h], qhf[kc], bl[h]);
                    MMA_BF16(sc[2 * p + h], qlf[kc], bh[h]);
                }
            }
        }

#pragma unroll
        for (int t = 0; t < 8; ++t) {
            float2 tv = *(const float2*)(tsp + t * 8 + (lane & 3) * 2);
            sc[t][0] = (sc[t][0] + tv.x) * 0.125f;
            sc[t][1] = (sc[t][1] + tv.y) * 0.125f;
            sc[t][2] = (sc[t][2] + tv.x) * 0.125f;
            sc[t][3] = (sc[t][3] + tv.y) * 0.125f;
        }

        float mx0 = -1e30f, mx1 = -1e30f;
#pragma unroll
        for (int t = 0; t < 8; ++t) {
            mx0 = fmaxf(mx0, fmaxf(sc[t][0], sc[t][1]));
            mx1 = fmaxf(mx1, fmaxf(sc[t][2], sc[t][3]));
        }
        mx0 = fmaxf(mx0, __shfl_xor_sync(0xffffffffu, mx0, 1));
        mx0 = fmaxf(mx0, __shfl_xor_sync(0xffffffffu, mx0, 2));
        mx1 = fmaxf(mx1, __shfl_xor_sync(0xffffffffu, mx1, 1));
        mx1 = fmaxf(mx1, __shfl_xor_sync(0xffffffffu, mx1, 2));
        const float nm0 = fmaxf(m0, mx0), nm1 = fmaxf(m1, mx1);
        const float a0 = __expf(m0 - nm0), a1 = __expf(m1 - nm1);
        m0 = nm0; m1 = nm1;

        float sum0 = 0.f, sum1 = 0.f;
#pragma unroll
        for (int t = 0; t < 8; ++t) {
            sc[t][0] = __expf(sc[t][0] - nm0);
            sc[t][1] = __expf(sc[t][1] - nm0);
            sc[t][2] = __expf(sc[t][2] - nm1);
            sc[t][3] = __expf(sc[t][3] - nm1);
            sum0 += sc[t][0] + sc[t][1];
            sum1 += sc[t][2] + sc[t][3];
        }
        sum0 += __shfl_xor_sync(0xffffffffu, sum0, 1);
        sum0 += __shfl_xor_sync(0xffffffffu, sum0, 2);
        sum1 += __shfl_xor_sync(0xffffffffu, sum1, 1);
        sum1 += __shfl_xor_sync(0xffffffffu, sum1, 2);
        l0 = l0 * a0 + sum0;
        l1 = l1 * a1 + sum1;
#pragma unroll
        for (int t = 0; t < 8; ++t) {
            o_[t][0] *= a0; o_[t][1] *= a0;
            o_[t][2] *= a1; o_[t][3] *= a1;
        }

#pragma unroll
        for (int kc = 0; kc < 4; ++kc) {
            uint32_t ah[4], al[4];
#pragma unroll
            for (int h = 0; h < 2; ++h) {
                const int t = 2 * kc + h;
                __nv_bfloat162 p01 = __floats2bfloat162_rn(sc[t][0], sc[t][1]);
                __nv_bfloat162 p23 = __floats2bfloat162_rn(sc[t][2], sc[t][3]);
                ah[2 * h + 0] = *(uint32_t*)&p01;
                ah[2 * h + 1] = *(uint32_t*)&p23;
                __nv_bfloat162 q01 = __floats2bfloat162_rn(
                    sc[t][0] - __bfloat162float(p01.x),
                    sc[t][1] - __bfloat162float(p01.y));
                __nv_bfloat162 q23 = __floats2bfloat162_rn(
                    sc[t][2] - __bfloat162float(p23.x),
                    sc[t][3] - __bfloat162float(p23.y));
                al[2 * h + 0] = *(uint32_t*)&q01;
                al[2 * h + 1] = *(uint32_t*)&q23;
            }
#pragma unroll
            for (int g = 0; g < 4; ++g) {
                int row = 16 * kc + ((sub & 1) << 3) + l7;
                int ch = 2 * g + (sub >> 1);
                uint32_t o = SWOFF(row, ch);
                uint32_t vh[2][2], vl[2][2];
                LDSM4T(vh[0][0], vh[0][1], vh[1][0], vh[1][1], st + 16384 + o);
                LDSM4T(vl[0][0], vl[0][1], vl[1][0], vl[1][1], st + 24576 + o);
#pragma unroll
                for (int h = 0; h < 2; ++h) {
                    MMA_BF16(o_[2 * g + h], ah, vh[h]);
                    MMA_BF16(o_[2 * g + h], ah, vl[h]);
                    MMA_BF16(o_[2 * g + h], al, vh[h]);
                }
            }
        }

        __syncthreads();
        if (jt + 2 < 16) load_stage(s, jt + 2);
        CP_ASYNC_COMMIT();
    }

    const float inv0 = 1.f / l0, inv1 = 1.f / l1;
    const int row0 = i0 + wid * 16 + (lane >> 2);
#pragma unroll
    for (int t = 0; t < 8; ++t) {
        const int col = n * DH + t * 8 + (lane & 3) * 2;
        float v0 = o_[t][0] * inv0, v1 = o_[t][1] * inv0;
        float v2 = o_[t][2] * inv1, v3 = o_[t][3] * inv1;
        __nv_bfloat162 h01 = __floats2bfloat162_rn(v0, v1);
        __nv_bfloat162 h23 = __floats2bfloat162_rn(v2, v3);
        size_t p0 = (size_t)(b * QL + row0) * DM + col;
        size_t p1 = (size_t)(b * QL + row0 + 8) * DM + col;
        *(__nv_bfloat162*)(avh + p0) = h01;
        *(__nv_bfloat162*)(avh + p1) = h23;
        *(__nv_bfloat162*)(avl + p0) = __floats2bfloat162_rn(
            v0 - __bfloat162float(h01.x), v1 - __bfloat162float(h01.y));
        *(__nv_bfloat162*)(avl + p1) = __floats2bfloat162_rn(
            v2 - __bfloat162float(h23.x), v3 - __bfloat162float(h23.y));
    }
}

// ===========================================================================
// Residual + LayerNorm
// ===========================================================================
__global__ __launch_bounds__(256) void ln_kernel(
    const float* __restrict__ w, const float* __restrict__ ao,
    const float* __restrict__ gamma, const float* __restrict__ beta,
    float* __restrict__ out)
{
    __shared__ float ssum[8], ssq[8];
    const int row = blockIdx.x;
    const int tid = threadIdx.x;
    const size_t base = (size_t)row * DM + tid * 4;

    float4 x = *(const float4*)(w + base);
    float4 a = *(const float4*)(ao + base);
    x.x += a.x; x.y += a.y; x.z += a.z; x.w += a.w;

    float sum = x.x + x.y + x.z + x.w;
    float sq = x.x * x.x + x.y * x.y + x.z * x.z + x.w * x.w;
#pragma unroll
    for (int off = 16; off; off >>= 1) {
        sum += __shfl_xor_sync(0xffffffffu, sum, off);
        sq += __shfl_xor_sync(0xffffffffu, sq, off);
    }
    const int wid = tid >> 5;
    if ((tid & 31) == 0) { ssum[wid] = sum; ssq[wid] = sq; }
    __syncthreads();
    sum = 0.f; sq = 0.f;
#pragma unroll
    for (int i = 0; i < 8; ++i) { sum += ssum[i]; sq += ssq[i]; }

    const float mu = sum * (1.f / DM);
    const float var = sq * (1.f / DM) - mu * mu;
    const float inv = rsqrtf(var + 1e-5f);

    float4 g = *(const float4*)(gamma + (size_t)tid * 4);
    float4 be = *(const float4*)(beta + (size_t)tid * 4);
    float4 r;
    r.x = (x.x - mu) * inv * g.x + be.x;
    r.y = (x.y - mu) * inv * g.y + be.y;
    r.z = (x.z - mu) * inv * g.z + be.z;
    r.w = (x.w - mu) * inv * g.w + be.w;
    *(float4*)(out + base) = r;
}

// ===========================================================================
extern "C" void kernel_launch(void* const* d_in, const int* in_sizes, int n_in,
                              void* d_out, int out_size)
{
    (void)in_sizes; (void)n_in; (void)out_size;
    const float* w      = (const float*)d_in[0];
    const float* r_emb  = (const float*)d_in[1];
    const float* r_w_b  = (const float*)d_in[2];
    const float* r_bias = (const float*)d_in[3];
    const float* Wq     = (const float*)d_in[4];
    const float* Wk     = (const float*)d_in[5];
    const float* Wv     = (const float*)d_in[6];
    const float* Wo     = (const float*)d_in[7];
    const float* gamma  = (const float*)d_in[8];
    const float* beta   = (const float*)d_in[9];
    float* out = (float*)d_out;

    float *ao, *tsg;
    __nv_bfloat16 *wh, *wl, *avh, *avl, *bh, *bl;
    __nv_bfloat16 *qbh, *qbl, *cbh, *cbl, *vbh, *vbl;
    cudaGetSymbolAddress((void**)&ao, g_ao);
    cudaGetSymbolAddress((void**)&wh, g_wh);
    cudaGetSymbolAddress((void**)&wl, g_wl);
    cudaGetSymbolAddress((void**)&avh, g_avh);
    cudaGetSymbolAddress((void**)&avl, g_avl);
    cudaGetSymbolAddress((void**)&bh, g_bh);
    cudaGetSymbolAddress((void**)&bl, g_bl);
    cudaGetSymbolAddress((void**)&qbh, g_qbh);
    cudaGetSymbolAddress((void**)&qbl, g_qbl);
    cudaGetSymbolAddress((void**)&cbh, g_cbh);
    cudaGetSymbolAddress((void**)&cbl, g_cbl);
    cudaGetSymbolAddress((void**)&vbh, g_vbh);
    cudaGetSymbolAddress((void**)&vbl, g_vbl);
    cudaGetSymbolAddress((void**)&tsg, g_ts);

    prep_all<<<dim3(32, 32, 8), 256>>>(w, Wq, Wk, Wv, Wo, wh, wl, bh, bl);

    cudaFuncSetAttribute(gemm_bf16x3,
                         cudaFuncAttributeMaxDynamicSharedMemorySize, SMEM_GEMM);
    // fused QKV with prep epilogues
    gemm_bf16x3<<<dim3(24, 32), 256, SMEM_GEMM>>>(
        wh, wl, bh, bl, nullptr, r_emb, r_w_b, r_bias,
        qbh, qbl, cbh, cbl, vbh, vbl, tsg, 1);

    cudaFuncSetAttribute(attn_mma,
                         cudaFuncAttributeMaxDynamicSharedMemorySize, ATT_SMEM);
    attn_mma<<<dim3(QL / 64, NHEAD, BB), 128, ATT_SMEM>>>(
        qbh, qbl, cbh, cbl, vbh, vbl, tsg, avh, avl);

    gemm_bf16x3<<<dim3(8, 32), 256, SMEM_GEMM>>>(
        avh, avl, bh + 3 * (size_t)DM * DM, bl + 3 * (size_t)DM * DM,
        ao, nullptr, nullptr, nullptr,
        nullptr, nullptr, nullptr, nullptr, nullptr, nullptr, nullptr, 0);

    ln_kernel<<<MTOT, 256>>>(w, ao, gamma, beta, out);
}